// round 12
// baseline (speedup 1.0000x reference)
#include <cuda_runtime.h>
#include <cuda_fp16.h>
#include <cstdint>

#define BATCH 4
#define SEQ 2048
#define DIM 1024
#define HEADS 16
#define DHEAD 64
#define INNER 1024
#define TOKENS (BATCH * SEQ)
#define ATT_SCALE 0.125f

// ---------------------------------------------------------------------------
// Scratch (allocation-free device globals) — all single fp16.
// ---------------------------------------------------------------------------
__device__ __half g_xw[TOKENS * DIM];
__device__ __half g_qw[TOKENS * INNER];
__device__ __half g_kw[TOKENS * INNER];
__device__ __half g_vw[TOKENS * INNER];
__device__ __half g_ow[TOKENS * INNER];
// fused QKV weight, transposed: rows 0-1023 = Wq^T, 1024-3071 = Wkv^T
__device__ __half g_wt[3 * INNER * DIM];
__device__ __half g_wot[DIM * INNER];

// ---------------------------------------------------------------------------
// Helpers (base-target PTX only: ldmatrix / mma.sync / cp.async)
// ---------------------------------------------------------------------------
__device__ __forceinline__ uint32_t smem_u32(const void* p) {
    uint32_t a;
    asm("{ .reg .u64 t; cvta.to.shared.u64 t, %1; cvt.u32.u64 %0, t; }"
        : "=r"(a) : "l"(p));
    return a;
}

__device__ __forceinline__ void ldm_x4(uint32_t* r, uint32_t addr) {
    asm volatile("ldmatrix.sync.aligned.m8n8.x4.shared.b16 {%0,%1,%2,%3}, [%4];"
                 : "=r"(r[0]), "=r"(r[1]), "=r"(r[2]), "=r"(r[3]) : "r"(addr));
}

__device__ __forceinline__ void ldm_x4_t(uint32_t* r, uint32_t addr) {
    asm volatile("ldmatrix.sync.aligned.m8n8.x4.trans.shared.b16 {%0,%1,%2,%3}, [%4];"
                 : "=r"(r[0]), "=r"(r[1]), "=r"(r[2]), "=r"(r[3]) : "r"(addr));
}

// fp16 inputs, fp32 accumulate
__device__ __forceinline__ void mma16816(float* c, const uint32_t* a, const uint32_t* b) {
    asm volatile(
        "mma.sync.aligned.m16n8k16.row.col.f32.f16.f16.f32 "
        "{%0,%1,%2,%3}, {%4,%5,%6,%7}, {%8,%9}, {%0,%1,%2,%3};"
        : "+f"(c[0]), "+f"(c[1]), "+f"(c[2]), "+f"(c[3])
        : "r"(a[0]), "r"(a[1]), "r"(a[2]), "r"(a[3]), "r"(b[0]), "r"(b[1]));
}

__device__ __forceinline__ void cp_async16(uint32_t saddr, const void* gaddr) {
    asm volatile("cp.async.cg.shared.global [%0], [%1], 16;"
                 :: "r"(saddr), "l"(gaddr) : "memory");
}
__device__ __forceinline__ void cp_commit() {
    asm volatile("cp.async.commit_group;" ::: "memory");
}
template <int N>
__device__ __forceinline__ void cp_wait() {
    asm volatile("cp.async.wait_group %0;" :: "n"(N) : "memory");
}

__device__ __forceinline__ uint32_t pack_h2(float x, float y) {
    __half2 H(__float2half_rn(x), __float2half_rn(y));
    return *(uint32_t*)&H;
}

// 128B-row swizzle (flash tiles): 8 x 16B chunks per row, chunk ^= row (mod 8)
#define FSWZ(row, chunk) (((row) << 7) + ((((chunk) ^ (row)) & 7) << 4))
// 64B-row swizzle (gemm tiles): 4 x 16B chunks per row, chunk ^= (row>>1)&3
#define HSWZ(row, chunk) (((row) << 6) + (((chunk) ^ (((row) >> 1) & 3)) << 4))

// ---------------------------------------------------------------------------
// Prep: cast x to fp16
// ---------------------------------------------------------------------------
__global__ void cast_x_kernel(const float* __restrict__ in,
                              __half* __restrict__ o) {
    int i = (blockIdx.x * blockDim.x + threadIdx.x) * 4;
    float4 v = *(const float4*)(in + i);
    *(uint32_t*)(o + i)     = pack_h2(v.x, v.y);
    *(uint32_t*)(o + i + 2) = pack_h2(v.z, v.w);
}

// ---------------------------------------------------------------------------
// Prep: transpose W[K,N] -> WT[N,K], single fp16
// ---------------------------------------------------------------------------
__global__ void transpose_h_kernel(const float* __restrict__ W,
                                   __half* __restrict__ WT,
                                   int K, int N) {
    __shared__ float t[32][33];
    int k0 = blockIdx.x * 32, n0 = blockIdx.y * 32;
    int x = threadIdx.x, y = threadIdx.y;
#pragma unroll
    for (int j = 0; j < 32; j += 8)
        t[y + j][x] = W[(size_t)(k0 + y + j) * N + n0 + x];
    __syncthreads();
#pragma unroll
    for (int j = 0; j < 32; j += 8)
        WT[(size_t)(n0 + y + j) * K + k0 + x] = __float2half_rn(t[x][y + j]);
}

// ---------------------------------------------------------------------------
// HMMA fp16 GEMM:  C[M,N] = A[M,K] @ BT[N,K]^T  (fp32 accumulate)
// CTA tile 128x256, 256 threads, 8 warps = 2(M) x 4(N), warp tile 64x64.
// Per k16 per warp: 8 LDSM.x4 feed 32 MMAs (ratio 4:1).
// k-block 32, 4-stage cp.async ring (96 KB). One sync per k-block.
// Output: fp32 Cf (+bias) if non-null; else QKV epilogue by 1024-col segment:
//   seg0 -> q fp16 scaled by ATT_SCALE; seg1 -> k fp16; seg2 -> v fp16.
// ---------------------------------------------------------------------------
#define HT_TK 32
#define HT_TILE_A 8192                   // [128 rows][32 fp16]
#define HT_TILE_B 16384                  // [256 rows][32 fp16]
#define HT_STAGE (HT_TILE_A + HT_TILE_B) // 24 KB
#define HT_NSTG 4
#define HT_SMEM (HT_NSTG * HT_STAGE)     // 96 KB

__global__ __launch_bounds__(256, 1)
void gemm_tc(const __half* __restrict__ Aw,
             const __half* __restrict__ Bw,
             float* __restrict__ Cf, const float* __restrict__ bias,
             __half* __restrict__ Sq, __half* __restrict__ Sk,
             __half* __restrict__ Sv,
             int N, int K)
{
    extern __shared__ char smem[];
    const uint32_t sb = smem_u32(smem);
    const int tid = threadIdx.x;
    const int wid = tid >> 5;
    const int lane = tid & 31;
    const int m0 = blockIdx.y * 128;
    const int n0 = blockIdx.x * 256;
    const int nkb = K / HT_TK;

    const int wm = (wid & 1) * 64;    // 2 M groups
    const int wn = (wid >> 1) * 64;   // 4 N groups

    // loader: A = 512 chunks (2/thread), B = 1024 chunks (4/thread)
    const int larow = tid >> 1;
    const int lach  = (tid & 1) * 2;
    const int lbrow = tid;

    auto load_stage = [&](int st, int kb) {
        const uint32_t stg = sb + st * HT_STAGE;
        const size_t kc = (size_t)kb * HT_TK;
        const __half* pa = Aw + (size_t)(m0 + larow) * K + kc;
#pragma unroll
        for (int c = 0; c < 2; c++)
            cp_async16(stg + HSWZ(larow, lach + c), pa + (lach + c) * 8);
        const uint32_t bstg = stg + HT_TILE_A;
        const __half* pb = Bw + (size_t)(n0 + lbrow) * K + kc;
#pragma unroll
        for (int c = 0; c < 4; c++)
            cp_async16(bstg + HSWZ(lbrow, c), pb + c * 8);
    };

    float acc[4][8][4];
#pragma unroll
    for (int i = 0; i < 4; i++)
#pragma unroll
        for (int j = 0; j < 8; j++)
#pragma unroll
            for (int e = 0; e < 4; e++) acc[i][j][e] = 0.f;

    const int a_row = lane & 15;
    const int a_chk = lane >> 4;
    const int b_row = (lane & 7) + ((lane >> 4) << 3);
    const int b_chk = (lane >> 3) & 1;

    load_stage(0, 0); cp_commit();
    load_stage(1, 1); cp_commit();
    load_stage(2, 2); cp_commit();

    for (int kb = 0; kb < nkb; kb++) {
        if (kb < nkb - 2)       cp_wait<2>();
        else if (kb == nkb - 2) cp_wait<1>();
        else                    cp_wait<0>();
        __syncthreads();

        if (kb + 3 < nkb) {
            load_stage((kb + 3) & (HT_NSTG - 1), kb + 3);
            cp_commit();
        }

        const uint32_t stg = sb + (kb & (HT_NSTG - 1)) * HT_STAGE;
        const uint32_t sAw = stg;
        const uint32_t sBw = stg + HT_TILE_A;

#pragma unroll
        for (int kk = 0; kk < 2; kk++) {
            uint32_t aw[4][4], bw[4][4];
#pragma unroll
            for (int mt = 0; mt < 4; mt++) {
                int r = wm + mt * 16 + a_row;
                int c = kk * 2 + a_chk;
                ldm_x4(aw[mt], sAw + HSWZ(r, c));
            }
#pragma unroll
            for (int ng = 0; ng < 4; ng++) {
                int r = wn + ng * 16 + b_row;
                int c = kk * 2 + b_chk;
                ldm_x4(bw[ng], sBw + HSWZ(r, c));
            }
#pragma unroll
            for (int mt = 0; mt < 4; mt++)
#pragma unroll
                for (int nt = 0; nt < 8; nt++)
                    mma16816(acc[mt][nt], aw[mt], &bw[nt >> 1][(nt & 1) * 2]);
        }
        __syncthreads();
    }

    const int erow = lane >> 2;
    const int ecol = (lane & 3) * 2;

    if (Cf) {
        // fp32 output with bias
#pragma unroll
        for (int mt = 0; mt < 4; mt++) {
#pragma unroll
            for (int nt = 0; nt < 8; nt++) {
                int gcol = n0 + wn + nt * 8 + ecol;
                float b0 = 0.f, b1 = 0.f;
                if (bias) { b0 = bias[gcol]; b1 = bias[gcol + 1]; }
                int r0 = m0 + wm + mt * 16 + erow;
                float2 v0 = make_float2(acc[mt][nt][0] + b0, acc[mt][nt][1] + b1);
                float2 v1 = make_float2(acc[mt][nt][2] + b0, acc[mt][nt][3] + b1);
                *(float2*)(Cf + (size_t)r0 * N + gcol)       = v0;
                *(float2*)(Cf + (size_t)(r0 + 8) * N + gcol) = v1;
            }
        }
    } else {
        // n0 is a multiple of 256 -> whole CTA stays in one 1024-col segment
        const int seg = n0 >> 10;      // 0:q  1:k  2:v
        const int c0 = n0 & 1023;
        const float sc = (seg == 0) ? ATT_SCALE : 1.0f;
        __half* D = (seg == 0) ? Sq : (seg == 1) ? Sk : Sv;
#pragma unroll
        for (int mt = 0; mt < 4; mt++) {
#pragma unroll
            for (int nt = 0; nt < 8; nt++) {
                int r0 = m0 + wm + mt * 16 + erow;
                int lcol = c0 + wn + nt * 8 + ecol;
                *(uint32_t*)(D + (size_t)r0 * 1024 + lcol) =
                    pack_h2(acc[mt][nt][0] * sc, acc[mt][nt][1] * sc);
                *(uint32_t*)(D + (size_t)(r0 + 8) * 1024 + lcol) =
                    pack_h2(acc[mt][nt][2] * sc, acc[mt][nt][3] * sc);
            }
        }
    }
}

// ---------------------------------------------------------------------------
// Flash attention on mma.sync, single fp16 Q/K/V/P (fp32 accumulate).
// CTA = 128 q rows x one (b,h). 8 warps, 16 rows each. K-chunks of 64,
// 3-stage cp.async KV ring. smem = 16 + 48 = 64 KB -> 2 CTAs/SM.
// ---------------------------------------------------------------------------
#define FA_BQ 128
#define FA_BK 64
#define FA_NC (SEQ / FA_BK)
#define FA_KVST 16384
#define FA_SMEM (16384 + 3 * FA_KVST)

__global__ __launch_bounds__(256, 2)
void flash_tc(const __half* __restrict__ Qw,
              const __half* __restrict__ Kw, const __half* __restrict__ Vw,
              __half* __restrict__ Ow)
{
    extern __shared__ char smem[];
    const uint32_t sb = smem_u32(smem);
    const int tid = threadIdx.x;
    const int wid = tid >> 5;
    const int lane = tid & 31;
    const int qt = blockIdx.x;
    const int b  = blockIdx.y >> 4;
    const int h  = blockIdx.y & 15;

    const size_t base_q  = (size_t)(b * SEQ + qt * FA_BQ) * INNER + h * DHEAD;
    const size_t base_kv = (size_t)b * SEQ * INNER + h * DHEAD;

    // ---- Q load (16 KB) ----
    {
        int row = tid >> 3, chunk = tid & 7;
#pragma unroll
        for (int p = 0; p < 4; p++) {
            int r = row + p * 32;
            cp_async16(sb + FSWZ(r, chunk), Qw + base_q + (size_t)r * INNER + chunk * 8);
        }
    }
    auto load_kv = [&](int st, int kc) {
        const uint32_t stg = sb + 16384 + st * FA_KVST;
        int row = tid >> 3, chunk = tid & 7;
        size_t gk = base_kv + (size_t)(kc * FA_BK) * INNER + chunk * 8;
#pragma unroll
        for (int p = 0; p < 2; p++) {
            int r = row + p * 32;
            size_t go = gk + (size_t)r * INNER;
            cp_async16(stg +        FSWZ(r, chunk), Kw + go);
            cp_async16(stg + 8192 + FSWZ(r, chunk), Vw + go);
        }
    };
    load_kv(0, 0); cp_commit();
    load_kv(1, 1); cp_commit();

    uint32_t qf[4][4];
    float oacc[8][4];
#pragma unroll
    for (int j = 0; j < 8; j++)
#pragma unroll
        for (int e = 0; e < 4; e++) oacc[j][e] = 0.f;
    float m0 = -1e30f, m1 = -1e30f, l0 = 0.f, l1 = 0.f;

    for (int kc = 0; kc < FA_NC; kc++) {
        if (kc + 1 < FA_NC) cp_wait<1>(); else cp_wait<0>();
        __syncthreads();

        if (kc == 0) {
#pragma unroll
            for (int kk = 0; kk < 4; kk++) {
                int r = wid * 16 + (lane & 15);
                int c = 2 * kk + (lane >> 4);
                ldm_x4(qf[kk], sb + FSWZ(r, c));
            }
        }
        const uint32_t stg = sb + 16384 + (kc % 3) * FA_KVST;

        // ---- S = Q @ K^T ----
        float sacc[8][4];
#pragma unroll
        for (int t = 0; t < 8; t++)
#pragma unroll
            for (int e = 0; e < 4; e++) sacc[t][e] = 0.f;
#pragma unroll
        for (int kk = 0; kk < 4; kk++) {
            uint32_t kb[4][4];
#pragma unroll
            for (int G = 0; G < 4; G++) {
                int r = 16 * G + ((lane >> 4) << 3) + (lane & 7);
                int c = 2 * kk + ((lane >> 3) & 1);
                ldm_x4(kb[G], stg + FSWZ(r, c));
            }
#pragma unroll
            for (int t = 0; t < 8; t++)
                mma16816(sacc[t], qf[kk], &kb[t >> 1][(t & 1) * 2]);
        }

        // ---- online softmax ----
        float mx0 = -1e30f, mx1 = -1e30f;
#pragma unroll
        for (int t = 0; t < 8; t++) {
            mx0 = fmaxf(mx0, fmaxf(sacc[t][0], sacc[t][1]));
            mx1 = fmaxf(mx1, fmaxf(sacc[t][2], sacc[t][3]));
        }
        mx0 = fmaxf(mx0, __shfl_xor_sync(0xffffffffu, mx0, 1));
        mx0 = fmaxf(mx0, __shfl_xor_sync(0xffffffffu, mx0, 2));
        mx1 = fmaxf(mx1, __shfl_xor_sync(0xffffffffu, mx1, 1));
        mx1 = fmaxf(mx1, __shfl_xor_sync(0xffffffffu, mx1, 2));
        float mn0 = fmaxf(m0, mx0), mn1 = fmaxf(m1, mx1);
        float a0 = __expf(m0 - mn0), a1 = __expf(m1 - mn1);
        m0 = mn0; m1 = mn1;
        float s0 = 0.f, s1 = 0.f;
#pragma unroll
        for (int t = 0; t < 8; t++) {
            sacc[t][0] = __expf(sacc[t][0] - mn0); s0 += sacc[t][0];
            sacc[t][1] = __expf(sacc[t][1] - mn0); s0 += sacc[t][1];
            sacc[t][2] = __expf(sacc[t][2] - mn1); s1 += sacc[t][2];
            sacc[t][3] = __expf(sacc[t][3] - mn1); s1 += sacc[t][3];
        }
        s0 += __shfl_xor_sync(0xffffffffu, s0, 1);
        s0 += __shfl_xor_sync(0xffffffffu, s0, 2);
        s1 += __shfl_xor_sync(0xffffffffu, s1, 1);
        s1 += __shfl_xor_sync(0xffffffffu, s1, 2);
        l0 = l0 * a0 + s0;
        l1 = l1 * a1 + s1;
#pragma unroll
        for (int j = 0; j < 8; j++) {
            oacc[j][0] *= a0; oacc[j][1] *= a0;
            oacc[j][2] *= a1; oacc[j][3] *= a1;
        }

        // ---- O += P @ V (P single fp16) ----
#pragma unroll
        for (int s = 0; s < 4; s++) {
            uint32_t ph[4];
            ph[0] = pack_h2(sacc[2 * s][0],     sacc[2 * s][1]);
            ph[1] = pack_h2(sacc[2 * s][2],     sacc[2 * s][3]);
            ph[2] = pack_h2(sacc[2 * s + 1][0], sacc[2 * s + 1][1]);
            ph[3] = pack_h2(sacc[2 * s + 1][2], sacc[2 * s + 1][3]);
            uint32_t vb[4][4];
#pragma unroll
            for (int J = 0; J < 4; J++) {
                int r = 16 * s + (lane & 7) + ((lane >> 3) & 1) * 8;
                int c = 2 * J + (lane >> 4);
                ldm_x4_t(vb[J], stg + 8192 + FSWZ(r, c));
            }
#pragma unroll
            for (int j = 0; j < 8; j++)
                mma16816(oacc[j], ph, &vb[j >> 1][(j & 1) * 2]);
        }

        if (kc + 2 < FA_NC) {
            load_kv((kc + 2) % 3, kc + 2);
            cp_commit();
        }
    }

    // ---- normalize + write O (single fp16) ----
    float inv0 = 1.f / l0, inv1 = 1.f / l1;
    int r = lane >> 2;
    size_t row0 = (size_t)(b * SEQ + qt * FA_BQ + wid * 16 + r);
    size_t row1 = row0 + 8;
    int colb = h * DHEAD + (lane & 3) * 2;
#pragma unroll
    for (int j = 0; j < 8; j++) {
        *(uint32_t*)(Ow + row0 * INNER + colb + j * 8) =
            pack_h2(oacc[j][0] * inv0, oacc[j][1] * inv0);
        *(uint32_t*)(Ow + row1 * INNER + colb + j * 8) =
            pack_h2(oacc[j][2] * inv1, oacc[j][3] * inv1);
    }
}

// ---------------------------------------------------------------------------
extern "C" void kernel_launch(void* const* d_in, const int* in_sizes, int n_in,
                              void* d_out, int out_size)
{
    const float* x   = (const float*)d_in[0];
    const float* Wq  = (const float*)d_in[1];
    const float* Wkv = (const float*)d_in[2];
    const float* Wo  = (const float*)d_in[3];
    const float* bo  = (const float*)d_in[4];
    float* out = (float*)d_out;

    __half *xw, *qw, *kw, *vw, *ow, *wt, *wot;
    cudaGetSymbolAddress((void**)&xw, g_xw);
    cudaGetSymbolAddress((void**)&qw, g_qw);
    cudaGetSymbolAddress((void**)&kw, g_kw);
    cudaGetSymbolAddress((void**)&vw, g_vw);
    cudaGetSymbolAddress((void**)&ow, g_ow);
    cudaGetSymbolAddress((void**)&wt, g_wt);
    cudaGetSymbolAddress((void**)&wot, g_wot);

    cudaFuncSetAttribute(gemm_tc, cudaFuncAttributeMaxDynamicSharedMemorySize, HT_SMEM);
    cudaFuncSetAttribute(flash_tc, cudaFuncAttributeMaxDynamicSharedMemorySize, FA_SMEM);

    // prep: cast x; transpose Wq/Wkv into fused [3072,1024] fp16 + Wo^T fp16
    cast_x_kernel<<<TOKENS * DIM / (256 * 4), 256>>>(x, xw);
    transpose_h_kernel<<<dim3(DIM / 32, INNER / 32), dim3(32, 8)>>>(
        Wq, wt, DIM, INNER);
    transpose_h_kernel<<<dim3(DIM / 32, 2 * INNER / 32), dim3(32, 8)>>>(
        Wkv, wt + (size_t)INNER * DIM, DIM, 2 * INNER);
    transpose_h_kernel<<<dim3(INNER / 32, DIM / 32), dim3(32, 8)>>>(
        Wo, wot, INNER, DIM);

    // fused [q|k|v] = x @ [Wq|Wkv]  (q scaled; fp16 out)
    gemm_tc<<<dim3(3 * INNER / 256, TOKENS / 128), 256, HT_SMEM>>>(
        xw, wt, nullptr, nullptr, qw, kw, vw, 3 * INNER, DIM);

    // attention on tensor cores
    flash_tc<<<dim3(SEQ / FA_BQ, BATCH * HEADS), 256, FA_SMEM>>>(qw, kw, vw, ow);

    // out = O @ Wo + bo  -> fp32
    gemm_tc<<<dim3(DIM / 256, TOKENS / 128), 256, HT_SMEM>>>(
        ow, wot, out, bo, nullptr, nullptr, nullptr, DIM, INNER);
}

// round 13
// speedup vs baseline: 1.1960x; 1.1960x over previous
#include <cuda_runtime.h>
#include <cuda_fp16.h>
#include <cstdint>

#define BATCH 4
#define SEQ 2048
#define DIM 1024
#define HEADS 16
#define DHEAD 64
#define INNER 1024
#define TOKENS (BATCH * SEQ)
// ATT_SCALE * log2(e): S lands directly in the exp2 domain
#define ATT_SCALE_LOG2E 0.18033688011112042f

// ---------------------------------------------------------------------------
// Scratch (allocation-free device globals) — all single fp16.
// ---------------------------------------------------------------------------
__device__ __half g_xw[TOKENS * DIM];
__device__ __half g_qw[TOKENS * INNER];
__device__ __half g_kw[TOKENS * INNER];
__device__ __half g_vw[TOKENS * INNER];
__device__ __half g_ow[TOKENS * INNER];
// fused QKV weight, transposed: rows 0-1023 = Wq^T, 1024-3071 = Wkv^T
__device__ __half g_wt[3 * INNER * DIM];
__device__ __half g_wot[DIM * INNER];

// ---------------------------------------------------------------------------
// Helpers (base-target PTX only: ldmatrix / mma.sync / cp.async)
// ---------------------------------------------------------------------------
__device__ __forceinline__ uint32_t smem_u32(const void* p) {
    uint32_t a;
    asm("{ .reg .u64 t; cvta.to.shared.u64 t, %1; cvt.u32.u64 %0, t; }"
        : "=r"(a) : "l"(p));
    return a;
}

__device__ __forceinline__ void ldm_x4(uint32_t* r, uint32_t addr) {
    asm volatile("ldmatrix.sync.aligned.m8n8.x4.shared.b16 {%0,%1,%2,%3}, [%4];"
                 : "=r"(r[0]), "=r"(r[1]), "=r"(r[2]), "=r"(r[3]) : "r"(addr));
}

__device__ __forceinline__ void ldm_x4_t(uint32_t* r, uint32_t addr) {
    asm volatile("ldmatrix.sync.aligned.m8n8.x4.trans.shared.b16 {%0,%1,%2,%3}, [%4];"
                 : "=r"(r[0]), "=r"(r[1]), "=r"(r[2]), "=r"(r[3]) : "r"(addr));
}

// fp16 inputs, fp32 accumulate
__device__ __forceinline__ void mma16816(float* c, const uint32_t* a, const uint32_t* b) {
    asm volatile(
        "mma.sync.aligned.m16n8k16.row.col.f32.f16.f16.f32 "
        "{%0,%1,%2,%3}, {%4,%5,%6,%7}, {%8,%9}, {%0,%1,%2,%3};"
        : "+f"(c[0]), "+f"(c[1]), "+f"(c[2]), "+f"(c[3])
        : "r"(a[0]), "r"(a[1]), "r"(a[2]), "r"(a[3]), "r"(b[0]), "r"(b[1]));
}

__device__ __forceinline__ void cp_async16(uint32_t saddr, const void* gaddr) {
    asm volatile("cp.async.cg.shared.global [%0], [%1], 16;"
                 :: "r"(saddr), "l"(gaddr) : "memory");
}
__device__ __forceinline__ void cp_commit() {
    asm volatile("cp.async.commit_group;" ::: "memory");
}
template <int N>
__device__ __forceinline__ void cp_wait() {
    asm volatile("cp.async.wait_group %0;" :: "n"(N) : "memory");
}

__device__ __forceinline__ float ex2f(float x) {
    float r;
    asm("ex2.approx.ftz.f32 %0, %1;" : "=f"(r) : "f"(x));
    return r;
}

__device__ __forceinline__ uint32_t pack_h2(float x, float y) {
    __half2 H(__float2half_rn(x), __float2half_rn(y));
    return *(uint32_t*)&H;
}

// 128B-row swizzle (flash tiles): 8 x 16B chunks per row, chunk ^= row (mod 8)
#define FSWZ(row, chunk) (((row) << 7) + ((((chunk) ^ (row)) & 7) << 4))
// 64B-row swizzle (gemm tiles): 4 x 16B chunks per row, chunk ^= (row>>1)&3
#define HSWZ(row, chunk) (((row) << 6) + (((chunk) ^ (((row) >> 1) & 3)) << 4))

// ---------------------------------------------------------------------------
// Prep: cast x to fp16
// ---------------------------------------------------------------------------
__global__ void cast_x_kernel(const float* __restrict__ in,
                              __half* __restrict__ o) {
    int i = (blockIdx.x * blockDim.x + threadIdx.x) * 4;
    float4 v = *(const float4*)(in + i);
    *(uint32_t*)(o + i)     = pack_h2(v.x, v.y);
    *(uint32_t*)(o + i + 2) = pack_h2(v.z, v.w);
}

// ---------------------------------------------------------------------------
// Prep: transpose W[K,N] -> WT[N,K], single fp16
// ---------------------------------------------------------------------------
__global__ void transpose_h_kernel(const float* __restrict__ W,
                                   __half* __restrict__ WT,
                                   int K, int N) {
    __shared__ float t[32][33];
    int k0 = blockIdx.x * 32, n0 = blockIdx.y * 32;
    int x = threadIdx.x, y = threadIdx.y;
#pragma unroll
    for (int j = 0; j < 32; j += 8)
        t[y + j][x] = W[(size_t)(k0 + y + j) * N + n0 + x];
    __syncthreads();
#pragma unroll
    for (int j = 0; j < 32; j += 8)
        WT[(size_t)(n0 + y + j) * K + k0 + x] = __float2half_rn(t[x][y + j]);
}

// ---------------------------------------------------------------------------
// HMMA fp16 GEMM:  C[M,N] = A[M,K] @ BT[N,K]^T  (fp32 accumulate)
// CTA tile 128x128, 512 threads, 16 warps = 4(M) x 4(N), warp tile 32x32.
// k-block 32, 4-stage cp.async ring (64 KB). ONE sync per k-block (the top
// barrier of iter kb already orders prefetch(kb+3) after compute(kb-1)).
// Output: fp32 Cf (+bias) if non-null; else QKV epilogue by 1024-col segment:
//   seg0 -> q fp16 scaled by ATT_SCALE*log2e; seg1 -> k fp16; seg2 -> v fp16.
// ---------------------------------------------------------------------------
#define HT_TK 32
#define HT_TILE 8192                     // [128 rows][32 fp16] = 8 KB
#define HT_STAGE (2 * HT_TILE)           // A + B = 16 KB
#define HT_NSTG 4
#define HT_SMEM (HT_NSTG * HT_STAGE)     // 64 KB

__global__ __launch_bounds__(512)
void gemm_tc(const __half* __restrict__ Aw,
             const __half* __restrict__ Bw,
             float* __restrict__ Cf, const float* __restrict__ bias,
             __half* __restrict__ Sq, __half* __restrict__ Sk,
             __half* __restrict__ Sv,
             int N, int K)
{
    extern __shared__ char smem[];
    const uint32_t sb = smem_u32(smem);
    const int tid = threadIdx.x;
    const int wid = tid >> 5;
    const int lane = tid & 31;
    const int m0 = blockIdx.y * 128;
    const int n0 = blockIdx.x * 128;
    const int nkb = K / HT_TK;

    const int wm = (wid & 3) * 32;
    const int wn = (wid >> 2) * 32;

    const int lrow = tid >> 2;
    const int lch  = tid & 3;
    const uint32_t lsw = HSWZ(lrow, lch);

    auto load_stage = [&](int st, int kb) {
        const uint32_t stg = sb + st * HT_STAGE;
        const size_t kc = (size_t)kb * HT_TK + lch * 8;
        cp_async16(stg + lsw,           Aw + (size_t)(m0 + lrow) * K + kc);
        cp_async16(stg + HT_TILE + lsw, Bw + (size_t)(n0 + lrow) * K + kc);
    };

    float acc[2][4][4];
#pragma unroll
    for (int i = 0; i < 2; i++)
#pragma unroll
        for (int j = 0; j < 4; j++)
#pragma unroll
            for (int e = 0; e < 4; e++) acc[i][j][e] = 0.f;

    const int a_row = lane & 15;
    const int a_chk = lane >> 4;
    const int b_row = (lane & 7) + ((lane >> 4) << 3);
    const int b_chk = (lane >> 3) & 1;

    load_stage(0, 0); cp_commit();
    load_stage(1, 1); cp_commit();
    load_stage(2, 2); cp_commit();

    for (int kb = 0; kb < nkb; kb++) {
        if (kb < nkb - 2)       cp_wait<2>();
        else if (kb == nkb - 2) cp_wait<1>();
        else                    cp_wait<0>();
        __syncthreads();   // also orders prefetch below vs compute of kb-1

        if (kb + 3 < nkb) {
            load_stage((kb + 3) & (HT_NSTG - 1), kb + 3);
            cp_commit();
        }

        const uint32_t stg = sb + (kb & (HT_NSTG - 1)) * HT_STAGE;
        const uint32_t sAw = stg;
        const uint32_t sBw = stg + HT_TILE;

#pragma unroll
        for (int kk = 0; kk < 2; kk++) {
            uint32_t aw[2][4], bw[2][4];
#pragma unroll
            for (int mt = 0; mt < 2; mt++) {
                int r = wm + mt * 16 + a_row;
                int c = kk * 2 + a_chk;
                ldm_x4(aw[mt], sAw + HSWZ(r, c));
            }
#pragma unroll
            for (int ng = 0; ng < 2; ng++) {
                int r = wn + ng * 16 + b_row;
                int c = kk * 2 + b_chk;
                ldm_x4(bw[ng], sBw + HSWZ(r, c));
            }
#pragma unroll
            for (int mt = 0; mt < 2; mt++)
#pragma unroll
                for (int nt = 0; nt < 4; nt++)
                    mma16816(acc[mt][nt], aw[mt], &bw[nt >> 1][(nt & 1) * 2]);
        }
        // no bottom barrier: next iteration's top barrier provides the ordering
    }

    const int erow = lane >> 2;
    const int ecol = (lane & 3) * 2;

    if (Cf) {
        // fp32 output with bias
#pragma unroll
        for (int mt = 0; mt < 2; mt++) {
#pragma unroll
            for (int nt = 0; nt < 4; nt++) {
                int gcol = n0 + wn + nt * 8 + ecol;
                float b0 = 0.f, b1 = 0.f;
                if (bias) { b0 = bias[gcol]; b1 = bias[gcol + 1]; }
                int r0 = m0 + wm + mt * 16 + erow;
                float2 v0 = make_float2(acc[mt][nt][0] + b0, acc[mt][nt][1] + b1);
                float2 v1 = make_float2(acc[mt][nt][2] + b0, acc[mt][nt][3] + b1);
                *(float2*)(Cf + (size_t)r0 * N + gcol)       = v0;
                *(float2*)(Cf + (size_t)(r0 + 8) * N + gcol) = v1;
            }
        }
    } else {
        const int seg = n0 >> 10;      // 0:q  1:k  2:v
        const int c0 = n0 & 1023;
        const float sc = (seg == 0) ? ATT_SCALE_LOG2E : 1.0f;
        __half* D = (seg == 0) ? Sq : (seg == 1) ? Sk : Sv;
#pragma unroll
        for (int mt = 0; mt < 2; mt++) {
#pragma unroll
            for (int nt = 0; nt < 4; nt++) {
                int r0 = m0 + wm + mt * 16 + erow;
                int lcol = c0 + wn + nt * 8 + ecol;
                *(uint32_t*)(D + (size_t)r0 * 1024 + lcol) =
                    pack_h2(acc[mt][nt][0] * sc, acc[mt][nt][1] * sc);
                *(uint32_t*)(D + (size_t)(r0 + 8) * 1024 + lcol) =
                    pack_h2(acc[mt][nt][2] * sc, acc[mt][nt][3] * sc);
            }
        }
    }
}

// ---------------------------------------------------------------------------
// Flash attention on mma.sync, single fp16 Q/K/V/P (fp32 accumulate).
// q pre-scaled by ATT_SCALE*log2e -> softmax runs in the exp2 domain
// (ex2.approx, no per-element multiply).
// CTA = 128 q rows x one (b,h). 8 warps, 16 rows each. K-chunks of 64,
// 3-stage cp.async KV ring. smem = 16 + 48 = 64 KB -> 2 CTAs/SM.
// ---------------------------------------------------------------------------
#define FA_BQ 128
#define FA_BK 64
#define FA_NC (SEQ / FA_BK)
#define FA_KVST 16384
#define FA_SMEM (16384 + 3 * FA_KVST)

__global__ __launch_bounds__(256, 2)
void flash_tc(const __half* __restrict__ Qw,
              const __half* __restrict__ Kw, const __half* __restrict__ Vw,
              __half* __restrict__ Ow)
{
    extern __shared__ char smem[];
    const uint32_t sb = smem_u32(smem);
    const int tid = threadIdx.x;
    const int wid = tid >> 5;
    const int lane = tid & 31;
    const int qt = blockIdx.x;
    const int b  = blockIdx.y >> 4;
    const int h  = blockIdx.y & 15;

    const size_t base_q  = (size_t)(b * SEQ + qt * FA_BQ) * INNER + h * DHEAD;
    const size_t base_kv = (size_t)b * SEQ * INNER + h * DHEAD;

    // ---- Q load (16 KB) ----
    {
        int row = tid >> 3, chunk = tid & 7;
#pragma unroll
        for (int p = 0; p < 4; p++) {
            int r = row + p * 32;
            cp_async16(sb + FSWZ(r, chunk), Qw + base_q + (size_t)r * INNER + chunk * 8);
        }
    }
    auto load_kv = [&](int st, int kc) {
        const uint32_t stg = sb + 16384 + st * FA_KVST;
        int row = tid >> 3, chunk = tid & 7;
        size_t gk = base_kv + (size_t)(kc * FA_BK) * INNER + chunk * 8;
#pragma unroll
        for (int p = 0; p < 2; p++) {
            int r = row + p * 32;
            size_t go = gk + (size_t)r * INNER;
            cp_async16(stg +        FSWZ(r, chunk), Kw + go);
            cp_async16(stg + 8192 + FSWZ(r, chunk), Vw + go);
        }
    };
    load_kv(0, 0); cp_commit();
    load_kv(1, 1); cp_commit();

    uint32_t qf[4][4];
    float oacc[8][4];
#pragma unroll
    for (int j = 0; j < 8; j++)
#pragma unroll
        for (int e = 0; e < 4; e++) oacc[j][e] = 0.f;
    float m0 = -1e30f, m1 = -1e30f, l0 = 0.f, l1 = 0.f;

    for (int kc = 0; kc < FA_NC; kc++) {
        if (kc + 1 < FA_NC) cp_wait<1>(); else cp_wait<0>();
        __syncthreads();

        if (kc == 0) {
#pragma unroll
            for (int kk = 0; kk < 4; kk++) {
                int r = wid * 16 + (lane & 15);
                int c = 2 * kk + (lane >> 4);
                ldm_x4(qf[kk], sb + FSWZ(r, c));
            }
        }
        const uint32_t stg = sb + 16384 + (kc % 3) * FA_KVST;

        // ---- S = Q @ K^T  (already in exp2 domain) ----
        float sacc[8][4];
#pragma unroll
        for (int t = 0; t < 8; t++)
#pragma unroll
            for (int e = 0; e < 4; e++) sacc[t][e] = 0.f;
#pragma unroll
        for (int kk = 0; kk < 4; kk++) {
            uint32_t kb[4][4];
#pragma unroll
            for (int G = 0; G < 4; G++) {
                int r = 16 * G + ((lane >> 4) << 3) + (lane & 7);
                int c = 2 * kk + ((lane >> 3) & 1);
                ldm_x4(kb[G], stg + FSWZ(r, c));
            }
#pragma unroll
            for (int t = 0; t < 8; t++)
                mma16816(sacc[t], qf[kk], &kb[t >> 1][(t & 1) * 2]);
        }

        // ---- online softmax (exp2 domain) ----
        float mx0 = -1e30f, mx1 = -1e30f;
#pragma unroll
        for (int t = 0; t < 8; t++) {
            mx0 = fmaxf(mx0, fmaxf(sacc[t][0], sacc[t][1]));
            mx1 = fmaxf(mx1, fmaxf(sacc[t][2], sacc[t][3]));
        }
        mx0 = fmaxf(mx0, __shfl_xor_sync(0xffffffffu, mx0, 1));
        mx0 = fmaxf(mx0, __shfl_xor_sync(0xffffffffu, mx0, 2));
        mx1 = fmaxf(mx1, __shfl_xor_sync(0xffffffffu, mx1, 1));
        mx1 = fmaxf(mx1, __shfl_xor_sync(0xffffffffu, mx1, 2));
        float mn0 = fmaxf(m0, mx0), mn1 = fmaxf(m1, mx1);
        float a0 = ex2f(m0 - mn0), a1 = ex2f(m1 - mn1);
        m0 = mn0; m1 = mn1;
        float s0 = 0.f, s1 = 0.f;
#pragma unroll
        for (int t = 0; t < 8; t++) {
            sacc[t][0] = ex2f(sacc[t][0] - mn0); s0 += sacc[t][0];
            sacc[t][1] = ex2f(sacc[t][1] - mn0); s0 += sacc[t][1];
            sacc[t][2] = ex2f(sacc[t][2] - mn1); s1 += sacc[t][2];
            sacc[t][3] = ex2f(sacc[t][3] - mn1); s1 += sacc[t][3];
        }
        s0 += __shfl_xor_sync(0xffffffffu, s0, 1);
        s0 += __shfl_xor_sync(0xffffffffu, s0, 2);
        s1 += __shfl_xor_sync(0xffffffffu, s1, 1);
        s1 += __shfl_xor_sync(0xffffffffu, s1, 2);
        l0 = l0 * a0 + s0;
        l1 = l1 * a1 + s1;
#pragma unroll
        for (int j = 0; j < 8; j++) {
            oacc[j][0] *= a0; oacc[j][1] *= a0;
            oacc[j][2] *= a1; oacc[j][3] *= a1;
        }

        // ---- O += P @ V (P single fp16) ----
#pragma unroll
        for (int s = 0; s < 4; s++) {
            uint32_t ph[4];
            ph[0] = pack_h2(sacc[2 * s][0],     sacc[2 * s][1]);
            ph[1] = pack_h2(sacc[2 * s][2],     sacc[2 * s][3]);
            ph[2] = pack_h2(sacc[2 * s + 1][0], sacc[2 * s + 1][1]);
            ph[3] = pack_h2(sacc[2 * s + 1][2], sacc[2 * s + 1][3]);
            uint32_t vb[4][4];
#pragma unroll
            for (int J = 0; J < 4; J++) {
                int r = 16 * s + (lane & 7) + ((lane >> 3) & 1) * 8;
                int c = 2 * J + (lane >> 4);
                ldm_x4_t(vb[J], stg + 8192 + FSWZ(r, c));
            }
#pragma unroll
            for (int j = 0; j < 8; j++)
                mma16816(oacc[j], ph, &vb[j >> 1][(j & 1) * 2]);
        }

        if (kc + 2 < FA_NC) {
            load_kv((kc + 2) % 3, kc + 2);
            cp_commit();
        }
    }

    // ---- normalize + write O (single fp16) ----
    float inv0 = 1.f / l0, inv1 = 1.f / l1;
    int r = lane >> 2;
    size_t row0 = (size_t)(b * SEQ + qt * FA_BQ + wid * 16 + r);
    size_t row1 = row0 + 8;
    int colb = h * DHEAD + (lane & 3) * 2;
#pragma unroll
    for (int j = 0; j < 8; j++) {
        *(uint32_t*)(Ow + row0 * INNER + colb + j * 8) =
            pack_h2(oacc[j][0] * inv0, oacc[j][1] * inv0);
        *(uint32_t*)(Ow + row1 * INNER + colb + j * 8) =
            pack_h2(oacc[j][2] * inv1, oacc[j][3] * inv1);
    }
}

// ---------------------------------------------------------------------------
extern "C" void kernel_launch(void* const* d_in, const int* in_sizes, int n_in,
                              void* d_out, int out_size)
{
    const float* x   = (const float*)d_in[0];
    const float* Wq  = (const float*)d_in[1];
    const float* Wkv = (const float*)d_in[2];
    const float* Wo  = (const float*)d_in[3];
    const float* bo  = (const float*)d_in[4];
    float* out = (float*)d_out;

    __half *xw, *qw, *kw, *vw, *ow, *wt, *wot;
    cudaGetSymbolAddress((void**)&xw, g_xw);
    cudaGetSymbolAddress((void**)&qw, g_qw);
    cudaGetSymbolAddress((void**)&kw, g_kw);
    cudaGetSymbolAddress((void**)&vw, g_vw);
    cudaGetSymbolAddress((void**)&ow, g_ow);
    cudaGetSymbolAddress((void**)&wt, g_wt);
    cudaGetSymbolAddress((void**)&wot, g_wot);

    cudaFuncSetAttribute(gemm_tc, cudaFuncAttributeMaxDynamicSharedMemorySize, HT_SMEM);
    cudaFuncSetAttribute(flash_tc, cudaFuncAttributeMaxDynamicSharedMemorySize, FA_SMEM);

    // prep: cast x; transpose Wq/Wkv into fused [3072,1024] fp16 + Wo^T fp16
    cast_x_kernel<<<TOKENS * DIM / (256 * 4), 256>>>(x, xw);
    transpose_h_kernel<<<dim3(DIM / 32, INNER / 32), dim3(32, 8)>>>(
        Wq, wt, DIM, INNER);
    transpose_h_kernel<<<dim3(DIM / 32, 2 * INNER / 32), dim3(32, 8)>>>(
        Wkv, wt + (size_t)INNER * DIM, DIM, 2 * INNER);
    transpose_h_kernel<<<dim3(INNER / 32, DIM / 32), dim3(32, 8)>>>(
        Wo, wot, INNER, DIM);

    // fused [q|k|v] = x @ [Wq|Wkv]  (q scaled by ATT_SCALE*log2e; fp16 out)
    gemm_tc<<<dim3(3 * INNER / 128, TOKENS / 128), 512, HT_SMEM>>>(
        xw, wt, nullptr, nullptr, qw, kw, vw, 3 * INNER, DIM);

    // attention on tensor cores (exp2-domain softmax)
    flash_tc<<<dim3(SEQ / FA_BQ, BATCH * HEADS), 256, FA_SMEM>>>(qw, kw, vw, ow);

    // out = O @ Wo + bo  -> fp32
    gemm_tc<<<dim3(DIM / 128, TOKENS / 128), 512, HT_SMEM>>>(
        ow, wot, out, bo, nullptr, nullptr, nullptr, DIM, INNER);
}

// round 14
// speedup vs baseline: 1.2002x; 1.0035x over previous
#include <cuda_runtime.h>
#include <cuda_fp16.h>
#include <cstdint>

#define BATCH 4
#define SEQ 2048
#define DIM 1024
#define HEADS 16
#define DHEAD 64
#define INNER 1024
#define TOKENS (BATCH * SEQ)
// ATT_SCALE * log2(e): S lands directly in the exp2 domain
#define ATT_SCALE_LOG2E 0.18033688011112042f

// ---------------------------------------------------------------------------
// Scratch (allocation-free device globals) — all single fp16.
// ---------------------------------------------------------------------------
__device__ __half g_xw[TOKENS * DIM];
__device__ __half g_qw[TOKENS * INNER];
__device__ __half g_kw[TOKENS * INNER];
__device__ __half g_vw[TOKENS * INNER];
__device__ __half g_ow[TOKENS * INNER];
// fused QKV weight, transposed: rows 0-1023 = Wq^T, 1024-3071 = Wkv^T
__device__ __half g_wt[3 * INNER * DIM];
__device__ __half g_wot[DIM * INNER];

// ---------------------------------------------------------------------------
// Helpers (base-target PTX only: ldmatrix / mma.sync / cp.async)
// ---------------------------------------------------------------------------
__device__ __forceinline__ uint32_t smem_u32(const void* p) {
    uint32_t a;
    asm("{ .reg .u64 t; cvta.to.shared.u64 t, %1; cvt.u32.u64 %0, t; }"
        : "=r"(a) : "l"(p));
    return a;
}

__device__ __forceinline__ void ldm_x4(uint32_t* r, uint32_t addr) {
    asm volatile("ldmatrix.sync.aligned.m8n8.x4.shared.b16 {%0,%1,%2,%3}, [%4];"
                 : "=r"(r[0]), "=r"(r[1]), "=r"(r[2]), "=r"(r[3]) : "r"(addr));
}

__device__ __forceinline__ void ldm_x4_t(uint32_t* r, uint32_t addr) {
    asm volatile("ldmatrix.sync.aligned.m8n8.x4.trans.shared.b16 {%0,%1,%2,%3}, [%4];"
                 : "=r"(r[0]), "=r"(r[1]), "=r"(r[2]), "=r"(r[3]) : "r"(addr));
}

// fp16 inputs, fp32 accumulate
__device__ __forceinline__ void mma16816(float* c, const uint32_t* a, const uint32_t* b) {
    asm volatile(
        "mma.sync.aligned.m16n8k16.row.col.f32.f16.f16.f32 "
        "{%0,%1,%2,%3}, {%4,%5,%6,%7}, {%8,%9}, {%0,%1,%2,%3};"
        : "+f"(c[0]), "+f"(c[1]), "+f"(c[2]), "+f"(c[3])
        : "r"(a[0]), "r"(a[1]), "r"(a[2]), "r"(a[3]), "r"(b[0]), "r"(b[1]));
}

__device__ __forceinline__ void cp_async16(uint32_t saddr, const void* gaddr) {
    asm volatile("cp.async.cg.shared.global [%0], [%1], 16;"
                 :: "r"(saddr), "l"(gaddr) : "memory");
}
__device__ __forceinline__ void cp_commit() {
    asm volatile("cp.async.commit_group;" ::: "memory");
}
template <int N>
__device__ __forceinline__ void cp_wait() {
    asm volatile("cp.async.wait_group %0;" :: "n"(N) : "memory");
}

__device__ __forceinline__ float ex2f(float x) {
    float r;
    asm("ex2.approx.ftz.f32 %0, %1;" : "=f"(r) : "f"(x));
    return r;
}

__device__ __forceinline__ uint32_t pack_h2(float x, float y) {
    __half2 H(__float2half_rn(x), __float2half_rn(y));
    return *(uint32_t*)&H;
}

// 128B-row swizzle (flash tiles): 8 x 16B chunks per row, chunk ^= row (mod 8)
#define FSWZ(row, chunk) (((row) << 7) + ((((chunk) ^ (row)) & 7) << 4))
// 64B-row swizzle (gemm tiles): 4 x 16B chunks per row, chunk ^= (row>>1)&3
#define HSWZ(row, chunk) (((row) << 6) + (((chunk) ^ (((row) >> 1) & 3)) << 4))

// ---------------------------------------------------------------------------
// Prep: cast x to fp16
// ---------------------------------------------------------------------------
__global__ void cast_x_kernel(const float* __restrict__ in,
                              __half* __restrict__ o) {
    int i = (blockIdx.x * blockDim.x + threadIdx.x) * 4;
    float4 v = *(const float4*)(in + i);
    *(uint32_t*)(o + i)     = pack_h2(v.x, v.y);
    *(uint32_t*)(o + i + 2) = pack_h2(v.z, v.w);
}

// ---------------------------------------------------------------------------
// Prep: transpose ALL THREE weights (fp32 -> fp16^T) in one launch.
// Block ranges: [0,1024) Wq (1024x1024), [1024,3072) Wkv (1024x2048),
// [3072,4096) Wo (1024x1024).
// ---------------------------------------------------------------------------
__device__ __forceinline__ void transpose_tile(const float* __restrict__ W,
                                               __half* __restrict__ WT,
                                               int K, int N, int bk, int bn) {
    __shared__ float t[32][33];
    int k0 = bk * 32, n0 = bn * 32;
    int x = threadIdx.x, y = threadIdx.y;
#pragma unroll
    for (int j = 0; j < 32; j += 8)
        t[y + j][x] = W[(size_t)(k0 + y + j) * N + n0 + x];
    __syncthreads();
#pragma unroll
    for (int j = 0; j < 32; j += 8)
        WT[(size_t)(n0 + y + j) * K + k0 + x] = __float2half_rn(t[x][y + j]);
}

__global__ void transpose_all_kernel(const float* __restrict__ Wq,
                                     const float* __restrict__ Wkv,
                                     const float* __restrict__ Wo,
                                     __half* __restrict__ WT,   // fused qkv^T
                                     __half* __restrict__ WoT) {
    int id = blockIdx.x;
    if (id < 1024) {
        transpose_tile(Wq, WT, DIM, INNER, id & 31, id >> 5);
    } else if (id < 3072) {
        int t = id - 1024;
        transpose_tile(Wkv, WT + (size_t)INNER * DIM, DIM, 2 * INNER,
                       t & 31, t >> 5);
    } else {
        int t = id - 3072;
        transpose_tile(Wo, WoT, INNER, DIM, t & 31, t >> 5);
    }
}

// ---------------------------------------------------------------------------
// HMMA fp16 GEMM:  C[M,N] = A[M,K] @ BT[N,K]^T  (fp32 accumulate)
// CTA tile 128x128, 512 threads, 16 warps = 4(M) x 4(N), warp tile 32x32.
// k-block 32, 4-stage cp.async ring (64 KB). ONE sync per k-block.
// Output: fp32 Cf (+bias) if non-null; else QKV epilogue by 1024-col segment:
//   seg0 -> q fp16 scaled by ATT_SCALE*log2e; seg1 -> k fp16; seg2 -> v fp16.
// ---------------------------------------------------------------------------
#define HT_TK 32
#define HT_TILE 8192                     // [128 rows][32 fp16] = 8 KB
#define HT_STAGE (2 * HT_TILE)           // A + B = 16 KB
#define HT_NSTG 4
#define HT_SMEM (HT_NSTG * HT_STAGE)     // 64 KB

__global__ __launch_bounds__(512)
void gemm_tc(const __half* __restrict__ Aw,
             const __half* __restrict__ Bw,
             float* __restrict__ Cf, const float* __restrict__ bias,
             __half* __restrict__ Sq, __half* __restrict__ Sk,
             __half* __restrict__ Sv,
             int N, int K)
{
    extern __shared__ char smem[];
    const uint32_t sb = smem_u32(smem);
    const int tid = threadIdx.x;
    const int wid = tid >> 5;
    const int lane = tid & 31;
    const int m0 = blockIdx.y * 128;
    const int n0 = blockIdx.x * 128;
    const int nkb = K / HT_TK;

    const int wm = (wid & 3) * 32;
    const int wn = (wid >> 2) * 32;

    const int lrow = tid >> 2;
    const int lch  = tid & 3;
    const uint32_t lsw = HSWZ(lrow, lch);

    auto load_stage = [&](int st, int kb) {
        const uint32_t stg = sb + st * HT_STAGE;
        const size_t kc = (size_t)kb * HT_TK + lch * 8;
        cp_async16(stg + lsw,           Aw + (size_t)(m0 + lrow) * K + kc);
        cp_async16(stg + HT_TILE + lsw, Bw + (size_t)(n0 + lrow) * K + kc);
    };

    float acc[2][4][4];
#pragma unroll
    for (int i = 0; i < 2; i++)
#pragma unroll
        for (int j = 0; j < 4; j++)
#pragma unroll
            for (int e = 0; e < 4; e++) acc[i][j][e] = 0.f;

    const int a_row = lane & 15;
    const int a_chk = lane >> 4;
    const int b_row = (lane & 7) + ((lane >> 4) << 3);
    const int b_chk = (lane >> 3) & 1;

    load_stage(0, 0); cp_commit();
    load_stage(1, 1); cp_commit();
    load_stage(2, 2); cp_commit();

    for (int kb = 0; kb < nkb; kb++) {
        if (kb < nkb - 2)       cp_wait<2>();
        else if (kb == nkb - 2) cp_wait<1>();
        else                    cp_wait<0>();
        __syncthreads();   // also orders prefetch below vs compute of kb-1

        if (kb + 3 < nkb) {
            load_stage((kb + 3) & (HT_NSTG - 1), kb + 3);
            cp_commit();
        }

        const uint32_t stg = sb + (kb & (HT_NSTG - 1)) * HT_STAGE;
        const uint32_t sAw = stg;
        const uint32_t sBw = stg + HT_TILE;

#pragma unroll
        for (int kk = 0; kk < 2; kk++) {
            uint32_t aw[2][4], bw[2][4];
#pragma unroll
            for (int mt = 0; mt < 2; mt++) {
                int r = wm + mt * 16 + a_row;
                int c = kk * 2 + a_chk;
                ldm_x4(aw[mt], sAw + HSWZ(r, c));
            }
#pragma unroll
            for (int ng = 0; ng < 2; ng++) {
                int r = wn + ng * 16 + b_row;
                int c = kk * 2 + b_chk;
                ldm_x4(bw[ng], sBw + HSWZ(r, c));
            }
#pragma unroll
            for (int mt = 0; mt < 2; mt++)
#pragma unroll
                for (int nt = 0; nt < 4; nt++)
                    mma16816(acc[mt][nt], aw[mt], &bw[nt >> 1][(nt & 1) * 2]);
        }
        // no bottom barrier: next iteration's top barrier provides the ordering
    }

    const int erow = lane >> 2;
    const int ecol = (lane & 3) * 2;

    if (Cf) {
        // fp32 output with bias
#pragma unroll
        for (int mt = 0; mt < 2; mt++) {
#pragma unroll
            for (int nt = 0; nt < 4; nt++) {
                int gcol = n0 + wn + nt * 8 + ecol;
                float b0 = 0.f, b1 = 0.f;
                if (bias) { b0 = bias[gcol]; b1 = bias[gcol + 1]; }
                int r0 = m0 + wm + mt * 16 + erow;
                float2 v0 = make_float2(acc[mt][nt][0] + b0, acc[mt][nt][1] + b1);
                float2 v1 = make_float2(acc[mt][nt][2] + b0, acc[mt][nt][3] + b1);
                *(float2*)(Cf + (size_t)r0 * N + gcol)       = v0;
                *(float2*)(Cf + (size_t)(r0 + 8) * N + gcol) = v1;
            }
        }
    } else {
        const int seg = n0 >> 10;      // 0:q  1:k  2:v
        const int c0 = n0 & 1023;
        const float sc = (seg == 0) ? ATT_SCALE_LOG2E : 1.0f;
        __half* D = (seg == 0) ? Sq : (seg == 1) ? Sk : Sv;
#pragma unroll
        for (int mt = 0; mt < 2; mt++) {
#pragma unroll
            for (int nt = 0; nt < 4; nt++) {
                int r0 = m0 + wm + mt * 16 + erow;
                int lcol = c0 + wn + nt * 8 + ecol;
                *(uint32_t*)(D + (size_t)r0 * 1024 + lcol) =
                    pack_h2(acc[mt][nt][0] * sc, acc[mt][nt][1] * sc);
                *(uint32_t*)(D + (size_t)(r0 + 8) * 1024 + lcol) =
                    pack_h2(acc[mt][nt][2] * sc, acc[mt][nt][3] * sc);
            }
        }
    }
}

// ---------------------------------------------------------------------------
// Flash attention on mma.sync, single fp16 Q/K/V/P (fp32 accumulate).
// q pre-scaled by ATT_SCALE*log2e -> exp2-domain softmax.
// CTA = 128 q rows x one (b,h). 8 warps, 16 rows each. K-chunks of 64,
// 4-stage cp.async KV ring, prefetch issued right after the top sync
// (3 chunks of look-ahead). smem = 16 + 64 = 80 KB -> 2 CTAs/SM.
// ---------------------------------------------------------------------------
#define FA_BQ 128
#define FA_BK 64
#define FA_NC (SEQ / FA_BK)
#define FA_KVST 16384
#define FA_NSTG 4
#define FA_SMEM (16384 + FA_NSTG * FA_KVST)

__global__ __launch_bounds__(256, 2)
void flash_tc(const __half* __restrict__ Qw,
              const __half* __restrict__ Kw, const __half* __restrict__ Vw,
              __half* __restrict__ Ow)
{
    extern __shared__ char smem[];
    const uint32_t sb = smem_u32(smem);
    const int tid = threadIdx.x;
    const int wid = tid >> 5;
    const int lane = tid & 31;
    const int qt = blockIdx.x;
    const int b  = blockIdx.y >> 4;
    const int h  = blockIdx.y & 15;

    const size_t base_q  = (size_t)(b * SEQ + qt * FA_BQ) * INNER + h * DHEAD;
    const size_t base_kv = (size_t)b * SEQ * INNER + h * DHEAD;

    // ---- Q load (16 KB, grouped with KV chunk 0) ----
    {
        int row = tid >> 3, chunk = tid & 7;
#pragma unroll
        for (int p = 0; p < 4; p++) {
            int r = row + p * 32;
            cp_async16(sb + FSWZ(r, chunk), Qw + base_q + (size_t)r * INNER + chunk * 8);
        }
    }
    auto load_kv = [&](int st, int kc) {
        const uint32_t stg = sb + 16384 + st * FA_KVST;
        int row = tid >> 3, chunk = tid & 7;
        size_t gk = base_kv + (size_t)(kc * FA_BK) * INNER + chunk * 8;
#pragma unroll
        for (int p = 0; p < 2; p++) {
            int r = row + p * 32;
            size_t go = gk + (size_t)r * INNER;
            cp_async16(stg +        FSWZ(r, chunk), Kw + go);
            cp_async16(stg + 8192 + FSWZ(r, chunk), Vw + go);
        }
    };
    load_kv(0, 0); cp_commit();
    load_kv(1, 1); cp_commit();
    load_kv(2, 2); cp_commit();

    uint32_t qf[4][4];
    float oacc[8][4];
#pragma unroll
    for (int j = 0; j < 8; j++)
#pragma unroll
        for (int e = 0; e < 4; e++) oacc[j][e] = 0.f;
    float m0 = -1e30f, m1 = -1e30f, l0 = 0.f, l1 = 0.f;

    for (int kc = 0; kc < FA_NC; kc++) {
        if (kc < FA_NC - 2)       cp_wait<2>();
        else if (kc == FA_NC - 2) cp_wait<1>();
        else                      cp_wait<0>();
        __syncthreads();   // all warps done with stage (kc+3)&3 (read at kc-1)

        // prefetch immediately: full compute phase covers the load latency
        if (kc + 3 < FA_NC) {
            load_kv((kc + 3) & (FA_NSTG - 1), kc + 3);
            cp_commit();
        }

        if (kc == 0) {
#pragma unroll
            for (int kk = 0; kk < 4; kk++) {
                int r = wid * 16 + (lane & 15);
                int c = 2 * kk + (lane >> 4);
                ldm_x4(qf[kk], sb + FSWZ(r, c));
            }
        }
        const uint32_t stg = sb + 16384 + (kc & (FA_NSTG - 1)) * FA_KVST;

        // ---- S = Q @ K^T  (already in exp2 domain) ----
        float sacc[8][4];
#pragma unroll
        for (int t = 0; t < 8; t++)
#pragma unroll
            for (int e = 0; e < 4; e++) sacc[t][e] = 0.f;
#pragma unroll
        for (int kk = 0; kk < 4; kk++) {
            uint32_t kb[4][4];
#pragma unroll
            for (int G = 0; G < 4; G++) {
                int r = 16 * G + ((lane >> 4) << 3) + (lane & 7);
                int c = 2 * kk + ((lane >> 3) & 1);
                ldm_x4(kb[G], stg + FSWZ(r, c));
            }
#pragma unroll
            for (int t = 0; t < 8; t++)
                mma16816(sacc[t], qf[kk], &kb[t >> 1][(t & 1) * 2]);
        }

        // ---- online softmax (exp2 domain) ----
        float mx0 = -1e30f, mx1 = -1e30f;
#pragma unroll
        for (int t = 0; t < 8; t++) {
            mx0 = fmaxf(mx0, fmaxf(sacc[t][0], sacc[t][1]));
            mx1 = fmaxf(mx1, fmaxf(sacc[t][2], sacc[t][3]));
        }
        mx0 = fmaxf(mx0, __shfl_xor_sync(0xffffffffu, mx0, 1));
        mx0 = fmaxf(mx0, __shfl_xor_sync(0xffffffffu, mx0, 2));
        mx1 = fmaxf(mx1, __shfl_xor_sync(0xffffffffu, mx1, 1));
        mx1 = fmaxf(mx1, __shfl_xor_sync(0xffffffffu, mx1, 2));
        float mn0 = fmaxf(m0, mx0), mn1 = fmaxf(m1, mx1);
        float a0 = ex2f(m0 - mn0), a1 = ex2f(m1 - mn1);
        m0 = mn0; m1 = mn1;
        float s0 = 0.f, s1 = 0.f;
#pragma unroll
        for (int t = 0; t < 8; t++) {
            sacc[t][0] = ex2f(sacc[t][0] - mn0); s0 += sacc[t][0];
            sacc[t][1] = ex2f(sacc[t][1] - mn0); s0 += sacc[t][1];
            sacc[t][2] = ex2f(sacc[t][2] - mn1); s1 += sacc[t][2];
            sacc[t][3] = ex2f(sacc[t][3] - mn1); s1 += sacc[t][3];
        }
        s0 += __shfl_xor_sync(0xffffffffu, s0, 1);
        s0 += __shfl_xor_sync(0xffffffffu, s0, 2);
        s1 += __shfl_xor_sync(0xffffffffu, s1, 1);
        s1 += __shfl_xor_sync(0xffffffffu, s1, 2);
        l0 = l0 * a0 + s0;
        l1 = l1 * a1 + s1;
#pragma unroll
        for (int j = 0; j < 8; j++) {
            oacc[j][0] *= a0; oacc[j][1] *= a0;
            oacc[j][2] *= a1; oacc[j][3] *= a1;
        }

        // ---- O += P @ V (P single fp16) ----
#pragma unroll
        for (int s = 0; s < 4; s++) {
            uint32_t ph[4];
            ph[0] = pack_h2(sacc[2 * s][0],     sacc[2 * s][1]);
            ph[1] = pack_h2(sacc[2 * s][2],     sacc[2 * s][3]);
            ph[2] = pack_h2(sacc[2 * s + 1][0], sacc[2 * s + 1][1]);
            ph[3] = pack_h2(sacc[2 * s + 1][2], sacc[2 * s + 1][3]);
            uint32_t vb[4][4];
#pragma unroll
            for (int J = 0; J < 4; J++) {
                int r = 16 * s + (lane & 7) + ((lane >> 3) & 1) * 8;
                int c = 2 * J + (lane >> 4);
                ldm_x4_t(vb[J], stg + 8192 + FSWZ(r, c));
            }
#pragma unroll
            for (int j = 0; j < 8; j++)
                mma16816(oacc[j], ph, &vb[j >> 1][(j & 1) * 2]);
        }
    }

    // ---- normalize + write O (single fp16) ----
    float inv0 = 1.f / l0, inv1 = 1.f / l1;
    int r = lane >> 2;
    size_t row0 = (size_t)(b * SEQ + qt * FA_BQ + wid * 16 + r);
    size_t row1 = row0 + 8;
    int colb = h * DHEAD + (lane & 3) * 2;
#pragma unroll
    for (int j = 0; j < 8; j++) {
        *(uint32_t*)(Ow + row0 * INNER + colb + j * 8) =
            pack_h2(oacc[j][0] * inv0, oacc[j][1] * inv0);
        *(uint32_t*)(Ow + row1 * INNER + colb + j * 8) =
            pack_h2(oacc[j][2] * inv1, oacc[j][3] * inv1);
    }
}

// ---------------------------------------------------------------------------
extern "C" void kernel_launch(void* const* d_in, const int* in_sizes, int n_in,
                              void* d_out, int out_size)
{
    const float* x   = (const float*)d_in[0];
    const float* Wq  = (const float*)d_in[1];
    const float* Wkv = (const float*)d_in[2];
    const float* Wo  = (const float*)d_in[3];
    const float* bo  = (const float*)d_in[4];
    float* out = (float*)d_out;

    __half *xw, *qw, *kw, *vw, *ow, *wt, *wot;
    cudaGetSymbolAddress((void**)&xw, g_xw);
    cudaGetSymbolAddress((void**)&qw, g_qw);
    cudaGetSymbolAddress((void**)&kw, g_kw);
    cudaGetSymbolAddress((void**)&vw, g_vw);
    cudaGetSymbolAddress((void**)&ow, g_ow);
    cudaGetSymbolAddress((void**)&wt, g_wt);
    cudaGetSymbolAddress((void**)&wot, g_wot);

    cudaFuncSetAttribute(gemm_tc, cudaFuncAttributeMaxDynamicSharedMemorySize, HT_SMEM);
    cudaFuncSetAttribute(flash_tc, cudaFuncAttributeMaxDynamicSharedMemorySize, FA_SMEM);

    // prep: cast x; one fused transpose launch for Wq/Wkv/Wo
    cast_x_kernel<<<TOKENS * DIM / (256 * 4), 256>>>(x, xw);
    transpose_all_kernel<<<4096, dim3(32, 8)>>>(Wq, Wkv, Wo, wt, wot);

    // fused [q|k|v] = x @ [Wq|Wkv]  (q scaled by ATT_SCALE*log2e; fp16 out)
    gemm_tc<<<dim3(3 * INNER / 128, TOKENS / 128), 512, HT_SMEM>>>(
        xw, wt, nullptr, nullptr, qw, kw, vw, 3 * INNER, DIM);

    // attention on tensor cores (exp2-domain softmax)
    flash_tc<<<dim3(SEQ / FA_BQ, BATCH * HEADS), 256, FA_SMEM>>>(qw, kw, vw, ow);

    // out = O @ Wo + bo  -> fp32
    gemm_tc<<<dim3(DIM / 128, TOKENS / 128), 512, HT_SMEM>>>(
        ow, wot, out, bo, nullptr, nullptr, nullptr, DIM, INNER);
}

// round 15
// speedup vs baseline: 1.2606x; 1.0503x over previous
#include <cuda_runtime.h>
#include <cuda_fp16.h>
#include <cstdint>

#define BATCH 4
#define SEQ 2048
#define DIM 1024
#define HEADS 16
#define DHEAD 64
#define INNER 1024
#define TOKENS (BATCH * SEQ)
// ATT_SCALE * log2(e): S lands directly in the exp2 domain
#define ATT_SCALE_LOG2E 0.18033688011112042f

// ---------------------------------------------------------------------------
// Scratch (allocation-free device globals) — all single fp16.
// ---------------------------------------------------------------------------
__device__ __half g_xw[TOKENS * DIM];
__device__ __half g_qw[TOKENS * INNER];
__device__ __half g_kw[TOKENS * INNER];
__device__ __half g_vw[TOKENS * INNER];
__device__ __half g_ow[TOKENS * INNER];
// fused QKV weight, transposed: rows 0-1023 = Wq^T, 1024-3071 = Wkv^T
__device__ __half g_wt[3 * INNER * DIM];
__device__ __half g_wot[DIM * INNER];

// ---------------------------------------------------------------------------
// Helpers (base-target PTX only: ldmatrix / mma.sync / cp.async)
// ---------------------------------------------------------------------------
__device__ __forceinline__ uint32_t smem_u32(const void* p) {
    uint32_t a;
    asm("{ .reg .u64 t; cvta.to.shared.u64 t, %1; cvt.u32.u64 %0, t; }"
        : "=r"(a) : "l"(p));
    return a;
}

__device__ __forceinline__ void ldm_x4(uint32_t* r, uint32_t addr) {
    asm volatile("ldmatrix.sync.aligned.m8n8.x4.shared.b16 {%0,%1,%2,%3}, [%4];"
                 : "=r"(r[0]), "=r"(r[1]), "=r"(r[2]), "=r"(r[3]) : "r"(addr));
}

__device__ __forceinline__ void ldm_x4_t(uint32_t* r, uint32_t addr) {
    asm volatile("ldmatrix.sync.aligned.m8n8.x4.trans.shared.b16 {%0,%1,%2,%3}, [%4];"
                 : "=r"(r[0]), "=r"(r[1]), "=r"(r[2]), "=r"(r[3]) : "r"(addr));
}

// fp16 inputs, fp32 accumulate
__device__ __forceinline__ void mma16816(float* c, const uint32_t* a, const uint32_t* b) {
    asm volatile(
        "mma.sync.aligned.m16n8k16.row.col.f32.f16.f16.f32 "
        "{%0,%1,%2,%3}, {%4,%5,%6,%7}, {%8,%9}, {%0,%1,%2,%3};"
        : "+f"(c[0]), "+f"(c[1]), "+f"(c[2]), "+f"(c[3])
        : "r"(a[0]), "r"(a[1]), "r"(a[2]), "r"(a[3]), "r"(b[0]), "r"(b[1]));
}

__device__ __forceinline__ void cp_async16(uint32_t saddr, const void* gaddr) {
    asm volatile("cp.async.cg.shared.global [%0], [%1], 16;"
                 :: "r"(saddr), "l"(gaddr) : "memory");
}
__device__ __forceinline__ void cp_commit() {
    asm volatile("cp.async.commit_group;" ::: "memory");
}
template <int N>
__device__ __forceinline__ void cp_wait() {
    asm volatile("cp.async.wait_group %0;" :: "n"(N) : "memory");
}

__device__ __forceinline__ float ex2f(float x) {
    float r;
    asm("ex2.approx.ftz.f32 %0, %1;" : "=f"(r) : "f"(x));
    return r;
}

__device__ __forceinline__ uint32_t pack_h2(float x, float y) {
    __half2 H(__float2half_rn(x), __float2half_rn(y));
    return *(uint32_t*)&H;
}

// 128B-row swizzle (flash tiles): 8 x 16B chunks per row, chunk ^= row (mod 8)
#define FSWZ(row, chunk) (((row) << 7) + ((((chunk) ^ (row)) & 7) << 4))
// 64B-row swizzle (gemm tiles): 4 x 16B chunks per row, chunk ^= (row>>1)&3
#define HSWZ(row, chunk) (((row) << 6) + (((chunk) ^ (((row) >> 1) & 3)) << 4))

// ---------------------------------------------------------------------------
// Prep: cast x to fp16
// ---------------------------------------------------------------------------
__global__ void cast_x_kernel(const float* __restrict__ in,
                              __half* __restrict__ o) {
    int i = (blockIdx.x * blockDim.x + threadIdx.x) * 4;
    float4 v = *(const float4*)(in + i);
    *(uint32_t*)(o + i)     = pack_h2(v.x, v.y);
    *(uint32_t*)(o + i + 2) = pack_h2(v.z, v.w);
}

// ---------------------------------------------------------------------------
// Prep: transpose ALL THREE weights (fp32 -> fp16^T) in one launch.
// ---------------------------------------------------------------------------
__device__ __forceinline__ void transpose_tile(const float* __restrict__ W,
                                               __half* __restrict__ WT,
                                               int K, int N, int bk, int bn) {
    __shared__ float t[32][33];
    int k0 = bk * 32, n0 = bn * 32;
    int x = threadIdx.x, y = threadIdx.y;
#pragma unroll
    for (int j = 0; j < 32; j += 8)
        t[y + j][x] = W[(size_t)(k0 + y + j) * N + n0 + x];
    __syncthreads();
#pragma unroll
    for (int j = 0; j < 32; j += 8)
        WT[(size_t)(n0 + y + j) * K + k0 + x] = __float2half_rn(t[x][y + j]);
}

__global__ void transpose_all_kernel(const float* __restrict__ Wq,
                                     const float* __restrict__ Wkv,
                                     const float* __restrict__ Wo,
                                     __half* __restrict__ WT,   // fused qkv^T
                                     __half* __restrict__ WoT) {
    int id = blockIdx.x;
    if (id < 1024) {
        transpose_tile(Wq, WT, DIM, INNER, id & 31, id >> 5);
    } else if (id < 3072) {
        int t = id - 1024;
        transpose_tile(Wkv, WT + (size_t)INNER * DIM, DIM, 2 * INNER,
                       t & 31, t >> 5);
    } else {
        int t = id - 3072;
        transpose_tile(Wo, WoT, INNER, DIM, t & 31, t >> 5);
    }
}

// ---------------------------------------------------------------------------
// HMMA fp16 GEMM:  C[M,N] = A[M,K] @ BT[N,K]^T  (fp32 accumulate)
// CTA tile 128(M)x64(N), 256 threads, 8 warps = 4(M) x 2(N), warp tile 32x32.
// k-block 32, 4-stage cp.async ring: stage = A 8KB + B 4KB = 12KB, 48KB total
// -> ~3 CTAs/SM (reg-bound) so barriers/waits overlap across CTAs.
// ONE sync per k-block. Output: fp32 Cf (+bias) if non-null; else QKV
// epilogue by 1024-col segment (q scaled by ATT_SCALE*log2e, k, v).
// ---------------------------------------------------------------------------
#define HT_TK 32
#define HT_TILE_A 8192                   // [128 rows][32 fp16]
#define HT_TILE_B 4096                   // [64 rows][32 fp16]
#define HT_STAGE (HT_TILE_A + HT_TILE_B) // 12 KB
#define HT_NSTG 4
#define HT_SMEM (HT_NSTG * HT_STAGE)     // 48 KB

__global__ __launch_bounds__(256)
void gemm_tc(const __half* __restrict__ Aw,
             const __half* __restrict__ Bw,
             float* __restrict__ Cf, const float* __restrict__ bias,
             __half* __restrict__ Sq, __half* __restrict__ Sk,
             __half* __restrict__ Sv,
             int N, int K)
{
    extern __shared__ char smem[];
    const uint32_t sb = smem_u32(smem);
    const int tid = threadIdx.x;
    const int wid = tid >> 5;
    const int lane = tid & 31;
    const int m0 = blockIdx.y * 128;
    const int n0 = blockIdx.x * 64;
    const int nkb = K / HT_TK;

    const int wm = (wid & 3) * 32;    // 4 M groups
    const int wn = (wid >> 2) * 32;   // 2 N groups

    // loaders: A 512 chunks (2/thread), B 256 chunks (1/thread)
    const int larow = tid >> 1;
    const int lach  = (tid & 1) * 2;
    const int lbrow = tid >> 2;
    const int lbch  = tid & 3;
    const uint32_t lbsw = HSWZ(lbrow, lbch);

    auto load_stage = [&](int st, int kb) {
        const uint32_t stg = sb + st * HT_STAGE;
        const size_t kc = (size_t)kb * HT_TK;
        const __half* pa = Aw + (size_t)(m0 + larow) * K + kc;
#pragma unroll
        for (int c = 0; c < 2; c++)
            cp_async16(stg + HSWZ(larow, lach + c), pa + (lach + c) * 8);
        cp_async16(stg + HT_TILE_A + lbsw,
                   Bw + (size_t)(n0 + lbrow) * K + kc + lbch * 8);
    };

    float acc[2][4][4];
#pragma unroll
    for (int i = 0; i < 2; i++)
#pragma unroll
        for (int j = 0; j < 4; j++)
#pragma unroll
            for (int e = 0; e < 4; e++) acc[i][j][e] = 0.f;

    const int a_row = lane & 15;
    const int a_chk = lane >> 4;
    const int b_row = (lane & 7) + ((lane >> 4) << 3);
    const int b_chk = (lane >> 3) & 1;

    load_stage(0, 0); cp_commit();
    load_stage(1, 1); cp_commit();
    load_stage(2, 2); cp_commit();

    for (int kb = 0; kb < nkb; kb++) {
        if (kb < nkb - 2)       cp_wait<2>();
        else if (kb == nkb - 2) cp_wait<1>();
        else                    cp_wait<0>();
        __syncthreads();   // also orders prefetch below vs compute of kb-1

        if (kb + 3 < nkb) {
            load_stage((kb + 3) & (HT_NSTG - 1), kb + 3);
            cp_commit();
        }

        const uint32_t stg = sb + (kb & (HT_NSTG - 1)) * HT_STAGE;
        const uint32_t sAw = stg;
        const uint32_t sBw = stg + HT_TILE_A;

#pragma unroll
        for (int kk = 0; kk < 2; kk++) {
            uint32_t aw[2][4], bw[2][4];
#pragma unroll
            for (int mt = 0; mt < 2; mt++) {
                int r = wm + mt * 16 + a_row;
                int c = kk * 2 + a_chk;
                ldm_x4(aw[mt], sAw + HSWZ(r, c));
            }
#pragma unroll
            for (int ng = 0; ng < 2; ng++) {
                int r = wn + ng * 16 + b_row;
                int c = kk * 2 + b_chk;
                ldm_x4(bw[ng], sBw + HSWZ(r, c));
            }
#pragma unroll
            for (int mt = 0; mt < 2; mt++)
#pragma unroll
                for (int nt = 0; nt < 4; nt++)
                    mma16816(acc[mt][nt], aw[mt], &bw[nt >> 1][(nt & 1) * 2]);
        }
        // no bottom barrier: next iteration's top barrier provides the ordering
    }

    const int erow = lane >> 2;
    const int ecol = (lane & 3) * 2;

    if (Cf) {
        // fp32 output with bias
#pragma unroll
        for (int mt = 0; mt < 2; mt++) {
#pragma unroll
            for (int nt = 0; nt < 4; nt++) {
                int gcol = n0 + wn + nt * 8 + ecol;
                float b0 = 0.f, b1 = 0.f;
                if (bias) { b0 = bias[gcol]; b1 = bias[gcol + 1]; }
                int r0 = m0 + wm + mt * 16 + erow;
                float2 v0 = make_float2(acc[mt][nt][0] + b0, acc[mt][nt][1] + b1);
                float2 v1 = make_float2(acc[mt][nt][2] + b0, acc[mt][nt][3] + b1);
                *(float2*)(Cf + (size_t)r0 * N + gcol)       = v0;
                *(float2*)(Cf + (size_t)(r0 + 8) * N + gcol) = v1;
            }
        }
    } else {
        // n0 multiple of 64 -> whole CTA in one 1024-col segment
        const int seg = n0 >> 10;      // 0:q  1:k  2:v
        const int c0 = n0 & 1023;
        const float sc = (seg == 0) ? ATT_SCALE_LOG2E : 1.0f;
        __half* D = (seg == 0) ? Sq : (seg == 1) ? Sk : Sv;
#pragma unroll
        for (int mt = 0; mt < 2; mt++) {
#pragma unroll
            for (int nt = 0; nt < 4; nt++) {
                int r0 = m0 + wm + mt * 16 + erow;
                int lcol = c0 + wn + nt * 8 + ecol;
                *(uint32_t*)(D + (size_t)r0 * 1024 + lcol) =
                    pack_h2(acc[mt][nt][0] * sc, acc[mt][nt][1] * sc);
                *(uint32_t*)(D + (size_t)(r0 + 8) * 1024 + lcol) =
                    pack_h2(acc[mt][nt][2] * sc, acc[mt][nt][3] * sc);
            }
        }
    }
}

// ---------------------------------------------------------------------------
// Flash attention on mma.sync, single fp16 Q/K/V/P (fp32 accumulate).
// Unchanged from R13 (202 us, tensor 56%).
// ---------------------------------------------------------------------------
#define FA_BQ 128
#define FA_BK 64
#define FA_NC (SEQ / FA_BK)
#define FA_KVST 16384
#define FA_NSTG 4
#define FA_SMEM (16384 + FA_NSTG * FA_KVST)

__global__ __launch_bounds__(256, 2)
void flash_tc(const __half* __restrict__ Qw,
              const __half* __restrict__ Kw, const __half* __restrict__ Vw,
              __half* __restrict__ Ow)
{
    extern __shared__ char smem[];
    const uint32_t sb = smem_u32(smem);
    const int tid = threadIdx.x;
    const int wid = tid >> 5;
    const int lane = tid & 31;
    const int qt = blockIdx.x;
    const int b  = blockIdx.y >> 4;
    const int h  = blockIdx.y & 15;

    const size_t base_q  = (size_t)(b * SEQ + qt * FA_BQ) * INNER + h * DHEAD;
    const size_t base_kv = (size_t)b * SEQ * INNER + h * DHEAD;

    {
        int row = tid >> 3, chunk = tid & 7;
#pragma unroll
        for (int p = 0; p < 4; p++) {
            int r = row + p * 32;
            cp_async16(sb + FSWZ(r, chunk), Qw + base_q + (size_t)r * INNER + chunk * 8);
        }
    }
    auto load_kv = [&](int st, int kc) {
        const uint32_t stg = sb + 16384 + st * FA_KVST;
        int row = tid >> 3, chunk = tid & 7;
        size_t gk = base_kv + (size_t)(kc * FA_BK) * INNER + chunk * 8;
#pragma unroll
        for (int p = 0; p < 2; p++) {
            int r = row + p * 32;
            size_t go = gk + (size_t)r * INNER;
            cp_async16(stg +        FSWZ(r, chunk), Kw + go);
            cp_async16(stg + 8192 + FSWZ(r, chunk), Vw + go);
        }
    };
    load_kv(0, 0); cp_commit();
    load_kv(1, 1); cp_commit();
    load_kv(2, 2); cp_commit();

    uint32_t qf[4][4];
    float oacc[8][4];
#pragma unroll
    for (int j = 0; j < 8; j++)
#pragma unroll
        for (int e = 0; e < 4; e++) oacc[j][e] = 0.f;
    float m0 = -1e30f, m1 = -1e30f, l0 = 0.f, l1 = 0.f;

    for (int kc = 0; kc < FA_NC; kc++) {
        if (kc < FA_NC - 2)       cp_wait<2>();
        else if (kc == FA_NC - 2) cp_wait<1>();
        else                      cp_wait<0>();
        __syncthreads();

        if (kc + 3 < FA_NC) {
            load_kv((kc + 3) & (FA_NSTG - 1), kc + 3);
            cp_commit();
        }

        if (kc == 0) {
#pragma unroll
            for (int kk = 0; kk < 4; kk++) {
                int r = wid * 16 + (lane & 15);
                int c = 2 * kk + (lane >> 4);
                ldm_x4(qf[kk], sb + FSWZ(r, c));
            }
        }
        const uint32_t stg = sb + 16384 + (kc & (FA_NSTG - 1)) * FA_KVST;

        // ---- S = Q @ K^T  (exp2 domain) ----
        float sacc[8][4];
#pragma unroll
        for (int t = 0; t < 8; t++)
#pragma unroll
            for (int e = 0; e < 4; e++) sacc[t][e] = 0.f;
#pragma unroll
        for (int kk = 0; kk < 4; kk++) {
            uint32_t kb[4][4];
#pragma unroll
            for (int G = 0; G < 4; G++) {
                int r = 16 * G + ((lane >> 4) << 3) + (lane & 7);
                int c = 2 * kk + ((lane >> 3) & 1);
                ldm_x4(kb[G], stg + FSWZ(r, c));
            }
#pragma unroll
            for (int t = 0; t < 8; t++)
                mma16816(sacc[t], qf[kk], &kb[t >> 1][(t & 1) * 2]);
        }

        // ---- online softmax (exp2 domain) ----
        float mx0 = -1e30f, mx1 = -1e30f;
#pragma unroll
        for (int t = 0; t < 8; t++) {
            mx0 = fmaxf(mx0, fmaxf(sacc[t][0], sacc[t][1]));
            mx1 = fmaxf(mx1, fmaxf(sacc[t][2], sacc[t][3]));
        }
        mx0 = fmaxf(mx0, __shfl_xor_sync(0xffffffffu, mx0, 1));
        mx0 = fmaxf(mx0, __shfl_xor_sync(0xffffffffu, mx0, 2));
        mx1 = fmaxf(mx1, __shfl_xor_sync(0xffffffffu, mx1, 1));
        mx1 = fmaxf(mx1, __shfl_xor_sync(0xffffffffu, mx1, 2));
        float mn0 = fmaxf(m0, mx0), mn1 = fmaxf(m1, mx1);
        float a0 = ex2f(m0 - mn0), a1 = ex2f(m1 - mn1);
        m0 = mn0; m1 = mn1;
        float s0 = 0.f, s1 = 0.f;
#pragma unroll
        for (int t = 0; t < 8; t++) {
            sacc[t][0] = ex2f(sacc[t][0] - mn0); s0 += sacc[t][0];
            sacc[t][1] = ex2f(sacc[t][1] - mn0); s0 += sacc[t][1];
            sacc[t][2] = ex2f(sacc[t][2] - mn1); s1 += sacc[t][2];
            sacc[t][3] = ex2f(sacc[t][3] - mn1); s1 += sacc[t][3];
        }
        s0 += __shfl_xor_sync(0xffffffffu, s0, 1);
        s0 += __shfl_xor_sync(0xffffffffu, s0, 2);
        s1 += __shfl_xor_sync(0xffffffffu, s1, 1);
        s1 += __shfl_xor_sync(0xffffffffu, s1, 2);
        l0 = l0 * a0 + s0;
        l1 = l1 * a1 + s1;
#pragma unroll
        for (int j = 0; j < 8; j++) {
            oacc[j][0] *= a0; oacc[j][1] *= a0;
            oacc[j][2] *= a1; oacc[j][3] *= a1;
        }

        // ---- O += P @ V (P single fp16) ----
#pragma unroll
        for (int s = 0; s < 4; s++) {
            uint32_t ph[4];
            ph[0] = pack_h2(sacc[2 * s][0],     sacc[2 * s][1]);
            ph[1] = pack_h2(sacc[2 * s][2],     sacc[2 * s][3]);
            ph[2] = pack_h2(sacc[2 * s + 1][0], sacc[2 * s + 1][1]);
            ph[3] = pack_h2(sacc[2 * s + 1][2], sacc[2 * s + 1][3]);
            uint32_t vb[4][4];
#pragma unroll
            for (int J = 0; J < 4; J++) {
                int r = 16 * s + (lane & 7) + ((lane >> 3) & 1) * 8;
                int c = 2 * J + (lane >> 4);
                ldm_x4_t(vb[J], stg + 8192 + FSWZ(r, c));
            }
#pragma unroll
            for (int j = 0; j < 8; j++)
                mma16816(oacc[j], ph, &vb[j >> 1][(j & 1) * 2]);
        }
    }

    // ---- normalize + write O (single fp16) ----
    float inv0 = 1.f / l0, inv1 = 1.f / l1;
    int r = lane >> 2;
    size_t row0 = (size_t)(b * SEQ + qt * FA_BQ + wid * 16 + r);
    size_t row1 = row0 + 8;
    int colb = h * DHEAD + (lane & 3) * 2;
#pragma unroll
    for (int j = 0; j < 8; j++) {
        *(uint32_t*)(Ow + row0 * INNER + colb + j * 8) =
            pack_h2(oacc[j][0] * inv0, oacc[j][1] * inv0);
        *(uint32_t*)(Ow + row1 * INNER + colb + j * 8) =
            pack_h2(oacc[j][2] * inv1, oacc[j][3] * inv1);
    }
}

// ---------------------------------------------------------------------------
extern "C" void kernel_launch(void* const* d_in, const int* in_sizes, int n_in,
                              void* d_out, int out_size)
{
    const float* x   = (const float*)d_in[0];
    const float* Wq  = (const float*)d_in[1];
    const float* Wkv = (const float*)d_in[2];
    const float* Wo  = (const float*)d_in[3];
    const float* bo  = (const float*)d_in[4];
    float* out = (float*)d_out;

    __half *xw, *qw, *kw, *vw, *ow, *wt, *wot;
    cudaGetSymbolAddress((void**)&xw, g_xw);
    cudaGetSymbolAddress((void**)&qw, g_qw);
    cudaGetSymbolAddress((void**)&kw, g_kw);
    cudaGetSymbolAddress((void**)&vw, g_vw);
    cudaGetSymbolAddress((void**)&ow, g_ow);
    cudaGetSymbolAddress((void**)&wt, g_wt);
    cudaGetSymbolAddress((void**)&wot, g_wot);

    cudaFuncSetAttribute(gemm_tc, cudaFuncAttributeMaxDynamicSharedMemorySize, HT_SMEM);
    cudaFuncSetAttribute(flash_tc, cudaFuncAttributeMaxDynamicSharedMemorySize, FA_SMEM);

    // prep: cast x; one fused transpose launch for Wq/Wkv/Wo
    cast_x_kernel<<<TOKENS * DIM / (256 * 4), 256>>>(x, xw);
    transpose_all_kernel<<<4096, dim3(32, 8)>>>(Wq, Wkv, Wo, wt, wot);

    // fused [q|k|v] = x @ [Wq|Wkv]  (q scaled by ATT_SCALE*log2e; fp16 out)
    gemm_tc<<<dim3(3 * INNER / 64, TOKENS / 128), 256, HT_SMEM>>>(
        xw, wt, nullptr, nullptr, qw, kw, vw, 3 * INNER, DIM);

    // attention on tensor cores (exp2-domain softmax)
    flash_tc<<<dim3(SEQ / FA_BQ, BATCH * HEADS), 256, FA_SMEM>>>(qw, kw, vw, ow);

    // out = O @ Wo + bo  -> fp32
    gemm_tc<<<dim3(DIM / 64, TOKENS / 128), 256, HT_SMEM>>>(
        ow, wot, out, bo, nullptr, nullptr, nullptr, DIM, INNER);
}

// round 16
// speedup vs baseline: 1.3065x; 1.0364x over previous
#include <cuda_runtime.h>
#include <cuda_fp16.h>
#include <cstdint>

#define BATCH 4
#define SEQ 2048
#define DIM 1024
#define HEADS 16
#define DHEAD 64
#define INNER 1024
#define TOKENS (BATCH * SEQ)
// ATT_SCALE * log2(e): S lands directly in the exp2 domain
#define ATT_SCALE_LOG2E 0.18033688011112042f

// ---------------------------------------------------------------------------
// Scratch (allocation-free device globals) — all single fp16.
// ---------------------------------------------------------------------------
__device__ __half g_xw[TOKENS * DIM];
__device__ __half g_qw[TOKENS * INNER];
__device__ __half g_kw[TOKENS * INNER];
__device__ __half g_vw[TOKENS * INNER];
__device__ __half g_ow[TOKENS * INNER];
// fused QKV weight, transposed: rows 0-1023 = Wq^T, 1024-3071 = Wkv^T
__device__ __half g_wt[3 * INNER * DIM];
__device__ __half g_wot[DIM * INNER];

// ---------------------------------------------------------------------------
// Helpers (base-target PTX only: ldmatrix / mma.sync / cp.async)
// ---------------------------------------------------------------------------
__device__ __forceinline__ uint32_t smem_u32(const void* p) {
    uint32_t a;
    asm("{ .reg .u64 t; cvta.to.shared.u64 t, %1; cvt.u32.u64 %0, t; }"
        : "=r"(a) : "l"(p));
    return a;
}

__device__ __forceinline__ void ldm_x4(uint32_t* r, uint32_t addr) {
    asm volatile("ldmatrix.sync.aligned.m8n8.x4.shared.b16 {%0,%1,%2,%3}, [%4];"
                 : "=r"(r[0]), "=r"(r[1]), "=r"(r[2]), "=r"(r[3]) : "r"(addr));
}

__device__ __forceinline__ void ldm_x4_t(uint32_t* r, uint32_t addr) {
    asm volatile("ldmatrix.sync.aligned.m8n8.x4.trans.shared.b16 {%0,%1,%2,%3}, [%4];"
                 : "=r"(r[0]), "=r"(r[1]), "=r"(r[2]), "=r"(r[3]) : "r"(addr));
}

// fp16 inputs, fp32 accumulate
__device__ __forceinline__ void mma16816(float* c, const uint32_t* a, const uint32_t* b) {
    asm volatile(
        "mma.sync.aligned.m16n8k16.row.col.f32.f16.f16.f32 "
        "{%0,%1,%2,%3}, {%4,%5,%6,%7}, {%8,%9}, {%0,%1,%2,%3};"
        : "+f"(c[0]), "+f"(c[1]), "+f"(c[2]), "+f"(c[3])
        : "r"(a[0]), "r"(a[1]), "r"(a[2]), "r"(a[3]), "r"(b[0]), "r"(b[1]));
}

__device__ __forceinline__ void cp_async16(uint32_t saddr, const void* gaddr) {
    asm volatile("cp.async.cg.shared.global [%0], [%1], 16;"
                 :: "r"(saddr), "l"(gaddr) : "memory");
}
__device__ __forceinline__ void cp_commit() {
    asm volatile("cp.async.commit_group;" ::: "memory");
}
template <int N>
__device__ __forceinline__ void cp_wait() {
    asm volatile("cp.async.wait_group %0;" :: "n"(N) : "memory");
}

__device__ __forceinline__ float ex2f(float x) {
    float r;
    asm("ex2.approx.ftz.f32 %0, %1;" : "=f"(r) : "f"(x));
    return r;
}

// packed fp16x2 exp2
__device__ __forceinline__ uint32_t h2ex2(uint32_t x) {
    uint32_t r;
    asm("ex2.approx.f16x2 %0, %1;" : "=r"(r) : "r"(x));
    return r;
}

__device__ __forceinline__ uint32_t hsub2(uint32_t a, uint32_t b) {
    uint32_t r;
    asm("sub.f16x2 %0, %1, %2;" : "=r"(r) : "r"(a), "r"(b));
    return r;
}

__device__ __forceinline__ uint32_t pack_h2(float x, float y) {
    __half2 H = __floats2half2_rn(x, y);
    return *(uint32_t*)&H;
}

// 128B-row swizzle (flash tiles): 8 x 16B chunks per row, chunk ^= row (mod 8)
#define FSWZ(row, chunk) (((row) << 7) + ((((chunk) ^ (row)) & 7) << 4))
// 64B-row swizzle (gemm tiles): 4 x 16B chunks per row, chunk ^= (row>>1)&3
#define HSWZ(row, chunk) (((row) << 6) + (((chunk) ^ (((row) >> 1) & 3)) << 4))

// ---------------------------------------------------------------------------
// Prep: cast x to fp16
// ---------------------------------------------------------------------------
__global__ void cast_x_kernel(const float* __restrict__ in,
                              __half* __restrict__ o) {
    int i = (blockIdx.x * blockDim.x + threadIdx.x) * 4;
    float4 v = *(const float4*)(in + i);
    *(uint32_t*)(o + i)     = pack_h2(v.x, v.y);
    *(uint32_t*)(o + i + 2) = pack_h2(v.z, v.w);
}

// ---------------------------------------------------------------------------
// Prep: transpose ALL THREE weights (fp32 -> fp16^T) in one launch.
// ---------------------------------------------------------------------------
__device__ __forceinline__ void transpose_tile(const float* __restrict__ W,
                                               __half* __restrict__ WT,
                                               int K, int N, int bk, int bn) {
    __shared__ float t[32][33];
    int k0 = bk * 32, n0 = bn * 32;
    int x = threadIdx.x, y = threadIdx.y;
#pragma unroll
    for (int j = 0; j < 32; j += 8)
        t[y + j][x] = W[(size_t)(k0 + y + j) * N + n0 + x];
    __syncthreads();
#pragma unroll
    for (int j = 0; j < 32; j += 8)
        WT[(size_t)(n0 + y + j) * K + k0 + x] = __float2half_rn(t[x][y + j]);
}

__global__ void transpose_all_kernel(const float* __restrict__ Wq,
                                     const float* __restrict__ Wkv,
                                     const float* __restrict__ Wo,
                                     __half* __restrict__ WT,   // fused qkv^T
                                     __half* __restrict__ WoT) {
    int id = blockIdx.x;
    if (id < 1024) {
        transpose_tile(Wq, WT, DIM, INNER, id & 31, id >> 5);
    } else if (id < 3072) {
        int t = id - 1024;
        transpose_tile(Wkv, WT + (size_t)INNER * DIM, DIM, 2 * INNER,
                       t & 31, t >> 5);
    } else {
        int t = id - 3072;
        transpose_tile(Wo, WoT, INNER, DIM, t & 31, t >> 5);
    }
}

// ---------------------------------------------------------------------------
// HMMA fp16 GEMM (unchanged from R14): CTA 128x64, 256 thr, 8 warps 4Mx2N,
// k-block 32, 4-stage ring (48 KB) -> ~3 CTAs/SM.
// ---------------------------------------------------------------------------
#define HT_TK 32
#define HT_TILE_A 8192                   // [128 rows][32 fp16]
#define HT_TILE_B 4096                   // [64 rows][32 fp16]
#define HT_STAGE (HT_TILE_A + HT_TILE_B) // 12 KB
#define HT_NSTG 4
#define HT_SMEM (HT_NSTG * HT_STAGE)     // 48 KB

__global__ __launch_bounds__(256)
void gemm_tc(const __half* __restrict__ Aw,
             const __half* __restrict__ Bw,
             float* __restrict__ Cf, const float* __restrict__ bias,
             __half* __restrict__ Sq, __half* __restrict__ Sk,
             __half* __restrict__ Sv,
             int N, int K)
{
    extern __shared__ char smem[];
    const uint32_t sb = smem_u32(smem);
    const int tid = threadIdx.x;
    const int wid = tid >> 5;
    const int lane = tid & 31;
    const int m0 = blockIdx.y * 128;
    const int n0 = blockIdx.x * 64;
    const int nkb = K / HT_TK;

    const int wm = (wid & 3) * 32;
    const int wn = (wid >> 2) * 32;

    const int larow = tid >> 1;
    const int lach  = (tid & 1) * 2;
    const int lbrow = tid >> 2;
    const int lbch  = tid & 3;
    const uint32_t lbsw = HSWZ(lbrow, lbch);

    auto load_stage = [&](int st, int kb) {
        const uint32_t stg = sb + st * HT_STAGE;
        const size_t kc = (size_t)kb * HT_TK;
        const __half* pa = Aw + (size_t)(m0 + larow) * K + kc;
#pragma unroll
        for (int c = 0; c < 2; c++)
            cp_async16(stg + HSWZ(larow, lach + c), pa + (lach + c) * 8);
        cp_async16(stg + HT_TILE_A + lbsw,
                   Bw + (size_t)(n0 + lbrow) * K + kc + lbch * 8);
    };

    float acc[2][4][4];
#pragma unroll
    for (int i = 0; i < 2; i++)
#pragma unroll
        for (int j = 0; j < 4; j++)
#pragma unroll
            for (int e = 0; e < 4; e++) acc[i][j][e] = 0.f;

    const int a_row = lane & 15;
    const int a_chk = lane >> 4;
    const int b_row = (lane & 7) + ((lane >> 4) << 3);
    const int b_chk = (lane >> 3) & 1;

    load_stage(0, 0); cp_commit();
    load_stage(1, 1); cp_commit();
    load_stage(2, 2); cp_commit();

    for (int kb = 0; kb < nkb; kb++) {
        if (kb < nkb - 2)       cp_wait<2>();
        else if (kb == nkb - 2) cp_wait<1>();
        else                    cp_wait<0>();
        __syncthreads();

        if (kb + 3 < nkb) {
            load_stage((kb + 3) & (HT_NSTG - 1), kb + 3);
            cp_commit();
        }

        const uint32_t stg = sb + (kb & (HT_NSTG - 1)) * HT_STAGE;
        const uint32_t sAw = stg;
        const uint32_t sBw = stg + HT_TILE_A;

#pragma unroll
        for (int kk = 0; kk < 2; kk++) {
            uint32_t aw[2][4], bw[2][4];
#pragma unroll
            for (int mt = 0; mt < 2; mt++) {
                int r = wm + mt * 16 + a_row;
                int c = kk * 2 + a_chk;
                ldm_x4(aw[mt], sAw + HSWZ(r, c));
            }
#pragma unroll
            for (int ng = 0; ng < 2; ng++) {
                int r = wn + ng * 16 + b_row;
                int c = kk * 2 + b_chk;
                ldm_x4(bw[ng], sBw + HSWZ(r, c));
            }
#pragma unroll
            for (int mt = 0; mt < 2; mt++)
#pragma unroll
                for (int nt = 0; nt < 4; nt++)
                    mma16816(acc[mt][nt], aw[mt], &bw[nt >> 1][(nt & 1) * 2]);
        }
    }

    const int erow = lane >> 2;
    const int ecol = (lane & 3) * 2;

    if (Cf) {
#pragma unroll
        for (int mt = 0; mt < 2; mt++) {
#pragma unroll
            for (int nt = 0; nt < 4; nt++) {
                int gcol = n0 + wn + nt * 8 + ecol;
                float b0 = 0.f, b1 = 0.f;
                if (bias) { b0 = bias[gcol]; b1 = bias[gcol + 1]; }
                int r0 = m0 + wm + mt * 16 + erow;
                float2 v0 = make_float2(acc[mt][nt][0] + b0, acc[mt][nt][1] + b1);
                float2 v1 = make_float2(acc[mt][nt][2] + b0, acc[mt][nt][3] + b1);
                *(float2*)(Cf + (size_t)r0 * N + gcol)       = v0;
                *(float2*)(Cf + (size_t)(r0 + 8) * N + gcol) = v1;
            }
        }
    } else {
        const int seg = n0 >> 10;      // 0:q  1:k  2:v
        const int c0 = n0 & 1023;
        const float sc = (seg == 0) ? ATT_SCALE_LOG2E : 1.0f;
        __half* D = (seg == 0) ? Sq : (seg == 1) ? Sk : Sv;
#pragma unroll
        for (int mt = 0; mt < 2; mt++) {
#pragma unroll
            for (int nt = 0; nt < 4; nt++) {
                int r0 = m0 + wm + mt * 16 + erow;
                int lcol = c0 + wn + nt * 8 + ecol;
                *(uint32_t*)(D + (size_t)r0 * 1024 + lcol) =
                    pack_h2(acc[mt][nt][0] * sc, acc[mt][nt][1] * sc);
                *(uint32_t*)(D + (size_t)(r0 + 8) * 1024 + lcol) =
                    pack_h2(acc[mt][nt][2] * sc, acc[mt][nt][3] * sc);
            }
        }
    }
}

// ---------------------------------------------------------------------------
// Flash attention: fp16x2 softmax (HSUB2 + ex2.f16x2) and row-sums computed
// by a ones-column MMA (l accumulated in fp32 inside the tensor core, with
// the same alpha rescaling as O -> P/l errors consistent).
// CTA = 128 q rows x one (b,h). 8 warps, 16 rows each. K-chunks of 64,
// 4-stage cp.async KV ring. smem = 16 + 64 = 80 KB -> 2 CTAs/SM.
// ---------------------------------------------------------------------------
#define FA_BQ 128
#define FA_BK 64
#define FA_NC (SEQ / FA_BK)
#define FA_KVST 16384
#define FA_NSTG 4
#define FA_SMEM (16384 + FA_NSTG * FA_KVST)

__global__ __launch_bounds__(256, 2)
void flash_tc(const __half* __restrict__ Qw,
              const __half* __restrict__ Kw, const __half* __restrict__ Vw,
              __half* __restrict__ Ow)
{
    extern __shared__ char smem[];
    const uint32_t sb = smem_u32(smem);
    const int tid = threadIdx.x;
    const int wid = tid >> 5;
    const int lane = tid & 31;
    const int qt = blockIdx.x;
    const int b  = blockIdx.y >> 4;
    const int h  = blockIdx.y & 15;

    const size_t base_q  = (size_t)(b * SEQ + qt * FA_BQ) * INNER + h * DHEAD;
    const size_t base_kv = (size_t)b * SEQ * INNER + h * DHEAD;

    {
        int row = tid >> 3, chunk = tid & 7;
#pragma unroll
        for (int p = 0; p < 4; p++) {
            int r = row + p * 32;
            cp_async16(sb + FSWZ(r, chunk), Qw + base_q + (size_t)r * INNER + chunk * 8);
        }
    }
    auto load_kv = [&](int st, int kc) {
        const uint32_t stg = sb + 16384 + st * FA_KVST;
        int row = tid >> 3, chunk = tid & 7;
        size_t gk = base_kv + (size_t)(kc * FA_BK) * INNER + chunk * 8;
#pragma unroll
        for (int p = 0; p < 2; p++) {
            int r = row + p * 32;
            size_t go = gk + (size_t)r * INNER;
            cp_async16(stg +        FSWZ(r, chunk), Kw + go);
            cp_async16(stg + 8192 + FSWZ(r, chunk), Vw + go);
        }
    };
    load_kv(0, 0); cp_commit();
    load_kv(1, 1); cp_commit();
    load_kv(2, 2); cp_commit();

    // constant B fragment of the ones-column matrix (col 0 = 1, cols 1-7 = 0)
    const uint32_t bone = ((lane >> 2) == 0) ? 0x3C003C00u : 0u;
    const uint32_t b_ones[2] = {bone, bone};

    uint32_t qf[4][4];
    float oacc[8][4];
    float lacc[4] = {0.f, 0.f, 0.f, 0.f};   // ones-column accumulator (l in col 0)
#pragma unroll
    for (int j = 0; j < 8; j++)
#pragma unroll
        for (int e = 0; e < 4; e++) oacc[j][e] = 0.f;
    float m0 = -1e30f, m1 = -1e30f;

    for (int kc = 0; kc < FA_NC; kc++) {
        if (kc < FA_NC - 2)       cp_wait<2>();
        else if (kc == FA_NC - 2) cp_wait<1>();
        else                      cp_wait<0>();
        __syncthreads();

        if (kc + 3 < FA_NC) {
            load_kv((kc + 3) & (FA_NSTG - 1), kc + 3);
            cp_commit();
        }

        if (kc == 0) {
#pragma unroll
            for (int kk = 0; kk < 4; kk++) {
                int r = wid * 16 + (lane & 15);
                int c = 2 * kk + (lane >> 4);
                ldm_x4(qf[kk], sb + FSWZ(r, c));
            }
        }
        const uint32_t stg = sb + 16384 + (kc & (FA_NSTG - 1)) * FA_KVST;

        // ---- S = Q @ K^T  (exp2 domain) ----
        float sacc[8][4];
#pragma unroll
        for (int t = 0; t < 8; t++)
#pragma unroll
            for (int e = 0; e < 4; e++) sacc[t][e] = 0.f;
#pragma unroll
        for (int kk = 0; kk < 4; kk++) {
            uint32_t kb[4][4];
#pragma unroll
            for (int G = 0; G < 4; G++) {
                int r = 16 * G + ((lane >> 4) << 3) + (lane & 7);
                int c = 2 * kk + ((lane >> 3) & 1);
                ldm_x4(kb[G], stg + FSWZ(r, c));
            }
#pragma unroll
            for (int t = 0; t < 8; t++)
                mma16816(sacc[t], qf[kk], &kb[t >> 1][(t & 1) * 2]);
        }

        // ---- max (fp32, as before) ----
        float mx0 = -1e30f, mx1 = -1e30f;
#pragma unroll
        for (int t = 0; t < 8; t++) {
            mx0 = fmaxf(mx0, fmaxf(sacc[t][0], sacc[t][1]));
            mx1 = fmaxf(mx1, fmaxf(sacc[t][2], sacc[t][3]));
        }
        mx0 = fmaxf(mx0, __shfl_xor_sync(0xffffffffu, mx0, 1));
        mx0 = fmaxf(mx0, __shfl_xor_sync(0xffffffffu, mx0, 2));
        mx1 = fmaxf(mx1, __shfl_xor_sync(0xffffffffu, mx1, 1));
        mx1 = fmaxf(mx1, __shfl_xor_sync(0xffffffffu, mx1, 2));
        float mn0 = fmaxf(m0, mx0), mn1 = fmaxf(m1, mx1);
        float a0 = ex2f(m0 - mn0), a1 = ex2f(m1 - mn1);
        m0 = mn0; m1 = mn1;

        // ---- P = ex2(S - mn) in packed fp16x2 (these ARE the PV A-frags) ----
        const uint32_t mn0h = pack_h2(mn0, mn0);
        const uint32_t mn1h = pack_h2(mn1, mn1);
        uint32_t ph0[8], ph1[8];
#pragma unroll
        for (int t = 0; t < 8; t++) {
            ph0[t] = h2ex2(hsub2(pack_h2(sacc[t][0], sacc[t][1]), mn0h));
            ph1[t] = h2ex2(hsub2(pack_h2(sacc[t][2], sacc[t][3]), mn1h));
        }

        // ---- rescale O and l by alpha ----
#pragma unroll
        for (int j = 0; j < 8; j++) {
            oacc[j][0] *= a0; oacc[j][1] *= a0;
            oacc[j][2] *= a1; oacc[j][3] *= a1;
        }
        lacc[0] *= a0; lacc[1] *= a0; lacc[2] *= a1; lacc[3] *= a1;

        // ---- O += P @ V ; l += P @ ones ----
#pragma unroll
        for (int s = 0; s < 4; s++) {
            uint32_t ah[4];
            ah[0] = ph0[2 * s];     ah[1] = ph1[2 * s];
            ah[2] = ph0[2 * s + 1]; ah[3] = ph1[2 * s + 1];
            uint32_t vb[4][4];
#pragma unroll
            for (int J = 0; J < 4; J++) {
                int r = 16 * s + (lane & 7) + ((lane >> 3) & 1) * 8;
                int c = 2 * J + (lane >> 4);
                ldm_x4_t(vb[J], stg + 8192 + FSWZ(r, c));
            }
#pragma unroll
            for (int j = 0; j < 8; j++)
                mma16816(oacc[j], ah, &vb[j >> 1][(j & 1) * 2]);
            mma16816(lacc, ah, b_ones);
        }
    }

    // ---- fetch l (col 0 lives in lane (row<<2), elems 0/2) and normalize ----
    float l0 = __shfl_sync(0xffffffffu, lacc[0], lane & ~3);
    float l1 = __shfl_sync(0xffffffffu, lacc[2], lane & ~3);
    float inv0 = 1.f / l0, inv1 = 1.f / l1;
    int r = lane >> 2;
    size_t row0 = (size_t)(b * SEQ + qt * FA_BQ + wid * 16 + r);
    size_t row1 = row0 + 8;
    int colb = h * DHEAD + (lane & 3) * 2;
#pragma unroll
    for (int j = 0; j < 8; j++) {
        *(uint32_t*)(Ow + row0 * INNER + colb + j * 8) =
            pack_h2(oacc[j][0] * inv0, oacc[j][1] * inv0);
        *(uint32_t*)(Ow + row1 * INNER + colb + j * 8) =
            pack_h2(oacc[j][2] * inv1, oacc[j][3] * inv1);
    }
}

// ---------------------------------------------------------------------------
extern "C" void kernel_launch(void* const* d_in, const int* in_sizes, int n_in,
                              void* d_out, int out_size)
{
    const float* x   = (const float*)d_in[0];
    const float* Wq  = (const float*)d_in[1];
    const float* Wkv = (const float*)d_in[2];
    const float* Wo  = (const float*)d_in[3];
    const float* bo  = (const float*)d_in[4];
    float* out = (float*)d_out;

    __half *xw, *qw, *kw, *vw, *ow, *wt, *wot;
    cudaGetSymbolAddress((void**)&xw, g_xw);
    cudaGetSymbolAddress((void**)&qw, g_qw);
    cudaGetSymbolAddress((void**)&kw, g_kw);
    cudaGetSymbolAddress((void**)&vw, g_vw);
    cudaGetSymbolAddress((void**)&ow, g_ow);
    cudaGetSymbolAddress((void**)&wt, g_wt);
    cudaGetSymbolAddress((void**)&wot, g_wot);

    cudaFuncSetAttribute(gemm_tc, cudaFuncAttributeMaxDynamicSharedMemorySize, HT_SMEM);
    cudaFuncSetAttribute(flash_tc, cudaFuncAttributeMaxDynamicSharedMemorySize, FA_SMEM);

    // prep: cast x; one fused transpose launch for Wq/Wkv/Wo
    cast_x_kernel<<<TOKENS * DIM / (256 * 4), 256>>>(x, xw);
    transpose_all_kernel<<<4096, dim3(32, 8)>>>(Wq, Wkv, Wo, wt, wot);

    // fused [q|k|v] = x @ [Wq|Wkv]  (q scaled by ATT_SCALE*log2e; fp16 out)
    gemm_tc<<<dim3(3 * INNER / 64, TOKENS / 128), 256, HT_SMEM>>>(
        xw, wt, nullptr, nullptr, qw, kw, vw, 3 * INNER, DIM);

    // attention on tensor cores (fp16x2 softmax, MMA row-sums)
    flash_tc<<<dim3(SEQ / FA_BQ, BATCH * HEADS), 256, FA_SMEM>>>(qw, kw, vw, ow);

    // out = O @ Wo + bo  -> fp32
    gemm_tc<<<dim3(DIM / 64, TOKENS / 128), 256, HT_SMEM>>>(
        ow, wot, out, bo, nullptr, nullptr, nullptr, DIM, INNER);
}

// round 17
// speedup vs baseline: 1.3423x; 1.0274x over previous
#include <cuda_runtime.h>
#include <cuda_fp16.h>
#include <cstdint>

#define BATCH 4
#define SEQ 2048
#define DIM 1024
#define HEADS 16
#define DHEAD 64
#define INNER 1024
#define TOKENS (BATCH * SEQ)
// ATT_SCALE * log2(e): S lands directly in the exp2 domain
#define ATT_SCALE_LOG2E 0.18033688011112042f

// ---------------------------------------------------------------------------
// Scratch (allocation-free device globals) — all single fp16.
// ---------------------------------------------------------------------------
__device__ __half g_xw[TOKENS * DIM];
__device__ __half g_qw[TOKENS * INNER];
__device__ __half g_kw[TOKENS * INNER];
__device__ __half g_vw[TOKENS * INNER];
__device__ __half g_ow[TOKENS * INNER];
// fused QKV weight, transposed: rows 0-1023 = Wq^T, 1024-3071 = Wkv^T
__device__ __half g_wt[3 * INNER * DIM];
__device__ __half g_wot[DIM * INNER];

// ---------------------------------------------------------------------------
// Helpers (base-target PTX only: ldmatrix / mma.sync / cp.async)
// ---------------------------------------------------------------------------
__device__ __forceinline__ uint32_t smem_u32(const void* p) {
    uint32_t a;
    asm("{ .reg .u64 t; cvta.to.shared.u64 t, %1; cvt.u32.u64 %0, t; }"
        : "=r"(a) : "l"(p));
    return a;
}

__device__ __forceinline__ void ldm_x4(uint32_t* r, uint32_t addr) {
    asm volatile("ldmatrix.sync.aligned.m8n8.x4.shared.b16 {%0,%1,%2,%3}, [%4];"
                 : "=r"(r[0]), "=r"(r[1]), "=r"(r[2]), "=r"(r[3]) : "r"(addr));
}

__device__ __forceinline__ void ldm_x4_t(uint32_t* r, uint32_t addr) {
    asm volatile("ldmatrix.sync.aligned.m8n8.x4.trans.shared.b16 {%0,%1,%2,%3}, [%4];"
                 : "=r"(r[0]), "=r"(r[1]), "=r"(r[2]), "=r"(r[3]) : "r"(addr));
}

// fp16 inputs, fp32 accumulate
__device__ __forceinline__ void mma16816(float* c, const uint32_t* a, const uint32_t* b) {
    asm volatile(
        "mma.sync.aligned.m16n8k16.row.col.f32.f16.f16.f32 "
        "{%0,%1,%2,%3}, {%4,%5,%6,%7}, {%8,%9}, {%0,%1,%2,%3};"
        : "+f"(c[0]), "+f"(c[1]), "+f"(c[2]), "+f"(c[3])
        : "r"(a[0]), "r"(a[1]), "r"(a[2]), "r"(a[3]), "r"(b[0]), "r"(b[1]));
}

__device__ __forceinline__ void cp_async16(uint32_t saddr, const void* gaddr) {
    asm volatile("cp.async.cg.shared.global [%0], [%1], 16;"
                 :: "r"(saddr), "l"(gaddr) : "memory");
}
__device__ __forceinline__ void cp_commit() {
    asm volatile("cp.async.commit_group;" ::: "memory");
}
template <int N>
__device__ __forceinline__ void cp_wait() {
    asm volatile("cp.async.wait_group %0;" :: "n"(N) : "memory");
}

__device__ __forceinline__ float ex2f(float x) {
    float r;
    asm("ex2.approx.ftz.f32 %0, %1;" : "=f"(r) : "f"(x));
    return r;
}

// packed fp16x2 exp2
__device__ __forceinline__ uint32_t h2ex2(uint32_t x) {
    uint32_t r;
    asm("ex2.approx.f16x2 %0, %1;" : "=r"(r) : "r"(x));
    return r;
}

__device__ __forceinline__ uint32_t hsub2(uint32_t a, uint32_t b) {
    uint32_t r;
    asm("sub.f16x2 %0, %1, %2;" : "=r"(r) : "r"(a), "r"(b));
    return r;
}

__device__ __forceinline__ uint32_t pack_h2(float x, float y) {
    __half2 H = __floats2half2_rn(x, y);
    return *(uint32_t*)&H;
}

// 128B-row swizzle (flash tiles): 8 x 16B chunks per row, chunk ^= row (mod 8)
#define FSWZ(row, chunk) (((row) << 7) + ((((chunk) ^ (row)) & 7) << 4))
// 64B-row swizzle (gemm tiles): 4 x 16B chunks per row, chunk ^= (row>>1)&3
#define HSWZ(row, chunk) (((row) << 6) + (((chunk) ^ (((row) >> 1) & 3)) << 4))

// ---------------------------------------------------------------------------
// Prep: cast x to fp16
// ---------------------------------------------------------------------------
__global__ void cast_x_kernel(const float* __restrict__ in,
                              __half* __restrict__ o) {
    int i = (blockIdx.x * blockDim.x + threadIdx.x) * 4;
    float4 v = *(const float4*)(in + i);
    *(uint32_t*)(o + i)     = pack_h2(v.x, v.y);
    *(uint32_t*)(o + i + 2) = pack_h2(v.z, v.w);
}

// ---------------------------------------------------------------------------
// Prep: transpose ALL THREE weights (fp32 -> fp16^T) in one launch.
// ---------------------------------------------------------------------------
__device__ __forceinline__ void transpose_tile(const float* __restrict__ W,
                                               __half* __restrict__ WT,
                                               int K, int N, int bk, int bn) {
    __shared__ float t[32][33];
    int k0 = bk * 32, n0 = bn * 32;
    int x = threadIdx.x, y = threadIdx.y;
#pragma unroll
    for (int j = 0; j < 32; j += 8)
        t[y + j][x] = W[(size_t)(k0 + y + j) * N + n0 + x];
    __syncthreads();
#pragma unroll
    for (int j = 0; j < 32; j += 8)
        WT[(size_t)(n0 + y + j) * K + k0 + x] = __float2half_rn(t[x][y + j]);
}

__global__ void transpose_all_kernel(const float* __restrict__ Wq,
                                     const float* __restrict__ Wkv,
                                     const float* __restrict__ Wo,
                                     __half* __restrict__ WT,   // fused qkv^T
                                     __half* __restrict__ WoT) {
    int id = blockIdx.x;
    if (id < 1024) {
        transpose_tile(Wq, WT, DIM, INNER, id & 31, id >> 5);
    } else if (id < 3072) {
        int t = id - 1024;
        transpose_tile(Wkv, WT + (size_t)INNER * DIM, DIM, 2 * INNER,
                       t & 31, t >> 5);
    } else {
        int t = id - 3072;
        transpose_tile(Wo, WoT, INNER, DIM, t & 31, t >> 5);
    }
}

// ---------------------------------------------------------------------------
// HMMA fp16 GEMM:  C[M,N] = A[M,K] @ BT[N,K]^T  (fp32 accumulate)
// CTA tile 128x128, 256 threads, 8 warps = 4(M) x 2(N), warp tile 32x64.
// Halves L2 traffic vs 128x64 tiles while keeping 2 CTAs/SM for overlap.
// k-block 32, 4-stage cp.async ring (64 KB). ONE sync per k-block.
// ---------------------------------------------------------------------------
#define HT_TK 32
#define HT_TILE 8192                     // [128 rows][32 fp16] = 8 KB
#define HT_STAGE (2 * HT_TILE)           // A + B = 16 KB
#define HT_NSTG 4
#define HT_SMEM (HT_NSTG * HT_STAGE)     // 64 KB

__global__ __launch_bounds__(256, 2)
void gemm_tc(const __half* __restrict__ Aw,
             const __half* __restrict__ Bw,
             float* __restrict__ Cf, const float* __restrict__ bias,
             __half* __restrict__ Sq, __half* __restrict__ Sk,
             __half* __restrict__ Sv,
             int N, int K)
{
    extern __shared__ char smem[];
    const uint32_t sb = smem_u32(smem);
    const int tid = threadIdx.x;
    const int wid = tid >> 5;
    const int lane = tid & 31;
    const int m0 = blockIdx.y * 128;
    const int n0 = blockIdx.x * 128;
    const int nkb = K / HT_TK;

    const int wm = (wid & 3) * 32;    // 4 M groups
    const int wn = (wid >> 2) * 64;   // 2 N groups

    // loaders: A/B each 128 rows x 4 chunks = 512 chunks -> 2 chunks/thread
    const int lrow = tid >> 1;
    const int lchb = (tid & 1) * 2;

    auto load_stage = [&](int st, int kb) {
        const uint32_t stg = sb + st * HT_STAGE;
        const size_t kc = (size_t)kb * HT_TK;
        const __half* pa = Aw + (size_t)(m0 + lrow) * K + kc;
        const __half* pb = Bw + (size_t)(n0 + lrow) * K + kc;
#pragma unroll
        for (int c = 0; c < 2; c++) {
            cp_async16(stg + HSWZ(lrow, lchb + c), pa + (lchb + c) * 8);
            cp_async16(stg + HT_TILE + HSWZ(lrow, lchb + c), pb + (lchb + c) * 8);
        }
    };

    float acc[2][8][4];
#pragma unroll
    for (int i = 0; i < 2; i++)
#pragma unroll
        for (int j = 0; j < 8; j++)
#pragma unroll
            for (int e = 0; e < 4; e++) acc[i][j][e] = 0.f;

    const int a_row = lane & 15;
    const int a_chk = lane >> 4;
    const int b_row = (lane & 7) + ((lane >> 4) << 3);
    const int b_chk = (lane >> 3) & 1;

    load_stage(0, 0); cp_commit();
    load_stage(1, 1); cp_commit();
    load_stage(2, 2); cp_commit();

    for (int kb = 0; kb < nkb; kb++) {
        if (kb < nkb - 2)       cp_wait<2>();
        else if (kb == nkb - 2) cp_wait<1>();
        else                    cp_wait<0>();
        __syncthreads();   // also orders prefetch below vs compute of kb-1

        if (kb + 3 < nkb) {
            load_stage((kb + 3) & (HT_NSTG - 1), kb + 3);
            cp_commit();
        }

        const uint32_t stg = sb + (kb & (HT_NSTG - 1)) * HT_STAGE;
        const uint32_t sAw = stg;
        const uint32_t sBw = stg + HT_TILE;

#pragma unroll
        for (int kk = 0; kk < 2; kk++) {
            uint32_t aw[2][4], bw[4][4];
#pragma unroll
            for (int mt = 0; mt < 2; mt++) {
                int r = wm + mt * 16 + a_row;
                int c = kk * 2 + a_chk;
                ldm_x4(aw[mt], sAw + HSWZ(r, c));
            }
#pragma unroll
            for (int ng = 0; ng < 4; ng++) {
                int r = wn + ng * 16 + b_row;
                int c = kk * 2 + b_chk;
                ldm_x4(bw[ng], sBw + HSWZ(r, c));
            }
#pragma unroll
            for (int mt = 0; mt < 2; mt++)
#pragma unroll
                for (int nt = 0; nt < 8; nt++)
                    mma16816(acc[mt][nt], aw[mt], &bw[nt >> 1][(nt & 1) * 2]);
        }
        // no bottom barrier: next iteration's top barrier provides the ordering
    }

    const int erow = lane >> 2;
    const int ecol = (lane & 3) * 2;

    if (Cf) {
        // fp32 output with bias
#pragma unroll
        for (int mt = 0; mt < 2; mt++) {
#pragma unroll
            for (int nt = 0; nt < 8; nt++) {
                int gcol = n0 + wn + nt * 8 + ecol;
                float b0 = 0.f, b1 = 0.f;
                if (bias) { b0 = bias[gcol]; b1 = bias[gcol + 1]; }
                int r0 = m0 + wm + mt * 16 + erow;
                float2 v0 = make_float2(acc[mt][nt][0] + b0, acc[mt][nt][1] + b1);
                float2 v1 = make_float2(acc[mt][nt][2] + b0, acc[mt][nt][3] + b1);
                *(float2*)(Cf + (size_t)r0 * N + gcol)       = v0;
                *(float2*)(Cf + (size_t)(r0 + 8) * N + gcol) = v1;
            }
        }
    } else {
        // n0 multiple of 128 -> whole CTA in one 1024-col segment
        const int seg = n0 >> 10;      // 0:q  1:k  2:v
        const int c0 = n0 & 1023;
        const float sc = (seg == 0) ? ATT_SCALE_LOG2E : 1.0f;
        __half* D = (seg == 0) ? Sq : (seg == 1) ? Sk : Sv;
#pragma unroll
        for (int mt = 0; mt < 2; mt++) {
#pragma unroll
            for (int nt = 0; nt < 8; nt++) {
                int r0 = m0 + wm + mt * 16 + erow;
                int lcol = c0 + wn + nt * 8 + ecol;
                *(uint32_t*)(D + (size_t)r0 * 1024 + lcol) =
                    pack_h2(acc[mt][nt][0] * sc, acc[mt][nt][1] * sc);
                *(uint32_t*)(D + (size_t)(r0 + 8) * 1024 + lcol) =
                    pack_h2(acc[mt][nt][2] * sc, acc[mt][nt][3] * sc);
            }
        }
    }
}

// ---------------------------------------------------------------------------
// Flash attention (unchanged from R15): fp16x2 softmax, MMA row-sums.
// ---------------------------------------------------------------------------
#define FA_BQ 128
#define FA_BK 64
#define FA_NC (SEQ / FA_BK)
#define FA_KVST 16384
#define FA_NSTG 4
#define FA_SMEM (16384 + FA_NSTG * FA_KVST)

__global__ __launch_bounds__(256, 2)
void flash_tc(const __half* __restrict__ Qw,
              const __half* __restrict__ Kw, const __half* __restrict__ Vw,
              __half* __restrict__ Ow)
{
    extern __shared__ char smem[];
    const uint32_t sb = smem_u32(smem);
    const int tid = threadIdx.x;
    const int wid = tid >> 5;
    const int lane = tid & 31;
    const int qt = blockIdx.x;
    const int b  = blockIdx.y >> 4;
    const int h  = blockIdx.y & 15;

    const size_t base_q  = (size_t)(b * SEQ + qt * FA_BQ) * INNER + h * DHEAD;
    const size_t base_kv = (size_t)b * SEQ * INNER + h * DHEAD;

    {
        int row = tid >> 3, chunk = tid & 7;
#pragma unroll
        for (int p = 0; p < 4; p++) {
            int r = row + p * 32;
            cp_async16(sb + FSWZ(r, chunk), Qw + base_q + (size_t)r * INNER + chunk * 8);
        }
    }
    auto load_kv = [&](int st, int kc) {
        const uint32_t stg = sb + 16384 + st * FA_KVST;
        int row = tid >> 3, chunk = tid & 7;
        size_t gk = base_kv + (size_t)(kc * FA_BK) * INNER + chunk * 8;
#pragma unroll
        for (int p = 0; p < 2; p++) {
            int r = row + p * 32;
            size_t go = gk + (size_t)r * INNER;
            cp_async16(stg +        FSWZ(r, chunk), Kw + go);
            cp_async16(stg + 8192 + FSWZ(r, chunk), Vw + go);
        }
    };
    load_kv(0, 0); cp_commit();
    load_kv(1, 1); cp_commit();
    load_kv(2, 2); cp_commit();

    // constant B fragment of the ones-column matrix (col 0 = 1, cols 1-7 = 0)
    const uint32_t bone = ((lane >> 2) == 0) ? 0x3C003C00u : 0u;
    const uint32_t b_ones[2] = {bone, bone};

    uint32_t qf[4][4];
    float oacc[8][4];
    float lacc[4] = {0.f, 0.f, 0.f, 0.f};
#pragma unroll
    for (int j = 0; j < 8; j++)
#pragma unroll
        for (int e = 0; e < 4; e++) oacc[j][e] = 0.f;
    float m0 = -1e30f, m1 = -1e30f;

    for (int kc = 0; kc < FA_NC; kc++) {
        if (kc < FA_NC - 2)       cp_wait<2>();
        else if (kc == FA_NC - 2) cp_wait<1>();
        else                      cp_wait<0>();
        __syncthreads();

        if (kc + 3 < FA_NC) {
            load_kv((kc + 3) & (FA_NSTG - 1), kc + 3);
            cp_commit();
        }

        if (kc == 0) {
#pragma unroll
            for (int kk = 0; kk < 4; kk++) {
                int r = wid * 16 + (lane & 15);
                int c = 2 * kk + (lane >> 4);
                ldm_x4(qf[kk], sb + FSWZ(r, c));
            }
        }
        const uint32_t stg = sb + 16384 + (kc & (FA_NSTG - 1)) * FA_KVST;

        // ---- S = Q @ K^T  (exp2 domain) ----
        float sacc[8][4];
#pragma unroll
        for (int t = 0; t < 8; t++)
#pragma unroll
            for (int e = 0; e < 4; e++) sacc[t][e] = 0.f;
#pragma unroll
        for (int kk = 0; kk < 4; kk++) {
            uint32_t kb[4][4];
#pragma unroll
            for (int G = 0; G < 4; G++) {
                int r = 16 * G + ((lane >> 4) << 3) + (lane & 7);
                int c = 2 * kk + ((lane >> 3) & 1);
                ldm_x4(kb[G], stg + FSWZ(r, c));
            }
#pragma unroll
            for (int t = 0; t < 8; t++)
                mma16816(sacc[t], qf[kk], &kb[t >> 1][(t & 1) * 2]);
        }

        // ---- max (fp32) ----
        float mx0 = -1e30f, mx1 = -1e30f;
#pragma unroll
        for (int t = 0; t < 8; t++) {
            mx0 = fmaxf(mx0, fmaxf(sacc[t][0], sacc[t][1]));
            mx1 = fmaxf(mx1, fmaxf(sacc[t][2], sacc[t][3]));
        }
        mx0 = fmaxf(mx0, __shfl_xor_sync(0xffffffffu, mx0, 1));
        mx0 = fmaxf(mx0, __shfl_xor_sync(0xffffffffu, mx0, 2));
        mx1 = fmaxf(mx1, __shfl_xor_sync(0xffffffffu, mx1, 1));
        mx1 = fmaxf(mx1, __shfl_xor_sync(0xffffffffu, mx1, 2));
        float mn0 = fmaxf(m0, mx0), mn1 = fmaxf(m1, mx1);
        float a0 = ex2f(m0 - mn0), a1 = ex2f(m1 - mn1);
        m0 = mn0; m1 = mn1;

        // ---- P = ex2(S - mn) in packed fp16x2 ----
        const uint32_t mn0h = pack_h2(mn0, mn0);
        const uint32_t mn1h = pack_h2(mn1, mn1);
        uint32_t ph0[8], ph1[8];
#pragma unroll
        for (int t = 0; t < 8; t++) {
            ph0[t] = h2ex2(hsub2(pack_h2(sacc[t][0], sacc[t][1]), mn0h));
            ph1[t] = h2ex2(hsub2(pack_h2(sacc[t][2], sacc[t][3]), mn1h));
        }

        // ---- rescale O and l by alpha ----
#pragma unroll
        for (int j = 0; j < 8; j++) {
            oacc[j][0] *= a0; oacc[j][1] *= a0;
            oacc[j][2] *= a1; oacc[j][3] *= a1;
        }
        lacc[0] *= a0; lacc[1] *= a0; lacc[2] *= a1; lacc[3] *= a1;

        // ---- O += P @ V ; l += P @ ones ----
#pragma unroll
        for (int s = 0; s < 4; s++) {
            uint32_t ah[4];
            ah[0] = ph0[2 * s];     ah[1] = ph1[2 * s];
            ah[2] = ph0[2 * s + 1]; ah[3] = ph1[2 * s + 1];
            uint32_t vb[4][4];
#pragma unroll
            for (int J = 0; J < 4; J++) {
                int r = 16 * s + (lane & 7) + ((lane >> 3) & 1) * 8;
                int c = 2 * J + (lane >> 4);
                ldm_x4_t(vb[J], stg + 8192 + FSWZ(r, c));
            }
#pragma unroll
            for (int j = 0; j < 8; j++)
                mma16816(oacc[j], ah, &vb[j >> 1][(j & 1) * 2]);
            mma16816(lacc, ah, b_ones);
        }
    }

    // ---- fetch l and normalize ----
    float l0 = __shfl_sync(0xffffffffu, lacc[0], lane & ~3);
    float l1 = __shfl_sync(0xffffffffu, lacc[2], lane & ~3);
    float inv0 = 1.f / l0, inv1 = 1.f / l1;
    int r = lane >> 2;
    size_t row0 = (size_t)(b * SEQ + qt * FA_BQ + wid * 16 + r);
    size_t row1 = row0 + 8;
    int colb = h * DHEAD + (lane & 3) * 2;
#pragma unroll
    for (int j = 0; j < 8; j++) {
        *(uint32_t*)(Ow + row0 * INNER + colb + j * 8) =
            pack_h2(oacc[j][0] * inv0, oacc[j][1] * inv0);
        *(uint32_t*)(Ow + row1 * INNER + colb + j * 8) =
            pack_h2(oacc[j][2] * inv1, oacc[j][3] * inv1);
    }
}

// ---------------------------------------------------------------------------
extern "C" void kernel_launch(void* const* d_in, const int* in_sizes, int n_in,
                              void* d_out, int out_size)
{
    const float* x   = (const float*)d_in[0];
    const float* Wq  = (const float*)d_in[1];
    const float* Wkv = (const float*)d_in[2];
    const float* Wo  = (const float*)d_in[3];
    const float* bo  = (const float*)d_in[4];
    float* out = (float*)d_out;

    __half *xw, *qw, *kw, *vw, *ow, *wt, *wot;
    cudaGetSymbolAddress((void**)&xw, g_xw);
    cudaGetSymbolAddress((void**)&qw, g_qw);
    cudaGetSymbolAddress((void**)&kw, g_kw);
    cudaGetSymbolAddress((void**)&vw, g_vw);
    cudaGetSymbolAddress((void**)&ow, g_ow);
    cudaGetSymbolAddress((void**)&wt, g_wt);
    cudaGetSymbolAddress((void**)&wot, g_wot);

    cudaFuncSetAttribute(gemm_tc, cudaFuncAttributeMaxDynamicSharedMemorySize, HT_SMEM);
    cudaFuncSetAttribute(flash_tc, cudaFuncAttributeMaxDynamicSharedMemorySize, FA_SMEM);

    // prep: cast x; one fused transpose launch for Wq/Wkv/Wo
    cast_x_kernel<<<TOKENS * DIM / (256 * 4), 256>>>(x, xw);
    transpose_all_kernel<<<4096, dim3(32, 8)>>>(Wq, Wkv, Wo, wt, wot);

    // fused [q|k|v] = x @ [Wq|Wkv]  (q scaled by ATT_SCALE*log2e; fp16 out)
    gemm_tc<<<dim3(3 * INNER / 128, TOKENS / 128), 256, HT_SMEM>>>(
        xw, wt, nullptr, nullptr, qw, kw, vw, 3 * INNER, DIM);

    // attention on tensor cores (fp16x2 softmax, MMA row-sums)
    flash_tc<<<dim3(SEQ / FA_BQ, BATCH * HEADS), 256, FA_SMEM>>>(qw, kw, vw, ow);

    // out = O @ Wo + bo  -> fp32
    gemm_tc<<<dim3(DIM / 128, TOKENS / 128), 256, HT_SMEM>>>(
        ow, wot, out, bo, nullptr, nullptr, nullptr, DIM, INNER);
}